// round 5
// baseline (speedup 1.0000x reference)
#include <cuda_runtime.h>
#include <math.h>

#define NN 4000
#define NE 60000
#define MDIM 16
#define CDIM 64
#define HDIM 64
#define NHEADS 8
#define ADIM 8
#define VCDIM 8
#define CEDIM 32

// ---- scratch (__device__ globals: no allocation allowed) ----
__device__ float g_ex[NE * NHEADS];          // exp(logits) per edge
__device__ float g_segsum[NN * NHEADS];      // softmax denominators
__device__ float g_e[NE * CEDIM];            // silu edge embeddings (pass1 -> pass2)
__device__ int   g_cnt[2];                   // bucket counters
__device__ int   g_order[NE];                // edge ids partitioned by blk
__device__ float g_WsT[2][HDIM * CDIM];      // WsT[h*64+c] = Ws[c*64+h]
__device__ float g_WtT[2][HDIM * CDIM];
__device__ float g_WeT[2][HDIM * CEDIM];     // WeT[h*32+ce] = We[ce*64+h]
__device__ float g_WaT[2][64 * HDIM];        // WaT[o*64+h] = Wa[h*64+o]
__device__ float g_PT [2][NHEADS * HDIM];    // PT[head*64+c] = sum_vc Wv[c,head*8+vc]*Wo[head*8+vc]

__device__ __forceinline__ float silu_f(float v) { return v / (1.0f + __expf(-v)); }

__device__ __forceinline__ int seli4(int kk, int a0, int a1, int a2, int a3) {
    int r = a0; if (kk == 1) r = a1; if (kk == 2) r = a2; if (kk == 3) r = a3; return r;
}
__device__ __forceinline__ float self4(int kk, float a0, float a1, float a2, float a3) {
    float r = a0; if (kk == 1) r = a1; if (kk == 2) r = a2; if (kk == 3) r = a3; return r;
}

// ---------------------------------------------------------------------------
// K0: zero accumulators + build derived small matrices
// ---------------------------------------------------------------------------
__global__ void setup_kernel(
    const float* __restrict__ fs_We, const float* __restrict__ fs_Ws, const float* __restrict__ fs_Wt,
    const float* __restrict__ fs_Wa,
    const float* __restrict__ fs_Wv, const float* __restrict__ fs_Wo,
    const float* __restrict__ dn_We, const float* __restrict__ dn_Ws, const float* __restrict__ dn_Wt,
    const float* __restrict__ dn_Wa,
    const float* __restrict__ dn_Wv, const float* __restrict__ dn_Wo,
    float* __restrict__ out)
{
    int tid = blockIdx.x * blockDim.x + threadIdx.x;
    int nt  = gridDim.x * blockDim.x;

    if (tid < 2) g_cnt[tid] = 0;
    for (int i = tid; i < NN * 3; i += nt) out[i] = 0.0f;
    for (int i = tid; i < NN * NHEADS; i += nt) g_segsum[i] = 0.0f;

    // WsT / WtT
    for (int i = tid; i < 2 * CDIM * HDIM; i += nt) {
        int blk = i >> 12; int r = i & 4095;
        int h = r >> 6; int c = r & 63;
        const float* Ws = blk ? dn_Ws : fs_Ws;
        const float* Wt = blk ? dn_Wt : fs_Wt;
        g_WsT[blk][h * CDIM + c] = Ws[c * HDIM + h];
        g_WtT[blk][h * CDIM + c] = Wt[c * HDIM + h];
    }
    // WeT
    for (int i = tid; i < 2 * HDIM * CEDIM; i += nt) {
        int blk = i >> 11; int r = i & 2047;
        int h = r >> 5; int ce = r & 31;
        const float* We = blk ? dn_We : fs_We;
        g_WeT[blk][h * CEDIM + ce] = We[ce * HDIM + h];
    }
    // WaT
    for (int i = tid; i < 2 * 64 * HDIM; i += nt) {
        int blk = i >> 12; int r = i & 4095;
        int o = r >> 6; int h = r & 63;
        const float* Wa = blk ? dn_Wa : fs_Wa;
        g_WaT[blk][o * HDIM + h] = Wa[h * 64 + o];
    }
    // PT
    for (int i = tid; i < 2 * NHEADS * HDIM; i += nt) {
        int blk = i >> 9; int r = i & 511;
        int h = r >> 6; int c = r & 63;
        const float* Wv = blk ? dn_Wv : fs_Wv;
        const float* Wo = blk ? dn_Wo : fs_Wo;
        float acc = 0.0f;
#pragma unroll
        for (int vc = 0; vc < VCDIM; vc++)
            acc += Wv[c * (NHEADS * VCDIM) + h * VCDIM + vc] * Wo[h * VCDIM + vc];
        g_PT[blk][h * HDIM + c] = acc;
    }
}

// ---------------------------------------------------------------------------
// K0b: bucket edges by blk = mask[dst].  blk0 ascending from 0, blk1
// descending from NE-1 -> two contiguous regions split at g_cnt[0].
// ---------------------------------------------------------------------------
__global__ void bucket_kernel(const int* __restrict__ eidx, const int* __restrict__ mask)
{
    int e = blockIdx.x * blockDim.x + threadIdx.x;
    bool valid = e < NE;
    int b = 0;
    if (valid) b = (mask[eidx[NE + e]] != 0) ? 1 : 0;
    unsigned m1 = __ballot_sync(0xffffffffu, valid && (b == 1));
    unsigned m0 = __ballot_sync(0xffffffffu, valid && (b == 0));
    int lane = threadIdx.x & 31;
    int base0 = 0, base1 = 0;
    if (lane == 0) {
        int n0 = __popc(m0), n1 = __popc(m1);
        if (n0) base0 = atomicAdd(&g_cnt[0], n0);
        if (n1) base1 = atomicAdd(&g_cnt[1], n1);
    }
    base0 = __shfl_sync(0xffffffffu, base0, 0);
    base1 = __shfl_sync(0xffffffffu, base1, 0);
    unsigned lt = (1u << lane) - 1u;
    if (valid) {
        int pos;
        if (b) pos = NE - 1 - (base1 + __popc(m1 & lt));
        else   pos = base0 + __popc(m0 & lt);
        g_order[pos] = e;
    }
}

// ---------------------------------------------------------------------------
// K1: logits + exp + segment sum.  One warp per 4 edges (blk-homogeneous
// except for at most one boundary group handled by the two-pass vmask path).
// ---------------------------------------------------------------------------
__global__ void __launch_bounds__(256)
pass1_kernel(
    const float* __restrict__ x, const int* __restrict__ zn,
    const float* __restrict__ dist, const int* __restrict__ eidx,
    const float* __restrict__ wig,
    const float* __restrict__ fs_emb_s, const float* __restrict__ fs_emb_t,
    const float* __restrict__ fs_wd, const float* __restrict__ fs_va,
    const float* __restrict__ dn_emb_s, const float* __restrict__ dn_emb_t,
    const float* __restrict__ dn_wd, const float* __restrict__ dn_va)
{
    __shared__ __align__(16) float sh_us[8][4][CDIM];
    __shared__ __align__(16) float sh_ut[8][4][CDIM];
    __shared__ __align__(16) float sh_e [8][4][CEDIM];
    __shared__ __align__(16) float sh_f0[8][4][HDIM];
    __shared__ float sh_d0[8][4][MDIM];

    const int w    = threadIdx.x >> 5;
    const int lane = threadIdx.x & 31;
    const int g    = blockIdx.x * 8 + w;   // group id, 0..14999
    const int base = g * 4;
    const int cnt0 = g_cnt[0];

    int eid[4], s[4], d[4];
#pragma unroll
    for (int k = 0; k < 4; k++) {
        eid[k] = g_order[base + k];
        s[k]   = eidx[eid[k]];
        d[k]   = eidx[NE + eid[k]];
    }

    auto process = [&](int bv, int vmask) {
        const float* emb_s = bv ? dn_emb_s : fs_emb_s;
        const float* emb_t = bv ? dn_emb_t : fs_emb_t;
        const float* wd    = bv ? dn_wd    : fs_wd;
        const float* va    = bv ? dn_va    : fs_va;

        // ---- D row 0 for all 4 edges ----
        {
            int k1 = lane >> 4;                 // 0/1
            int n  = lane & 15;
            int ea = k1 ? eid[1] : eid[0];
            int eb = k1 ? eid[3] : eid[2];
            sh_d0[w][k1][n]     = wig[(size_t)ea * 256 + n];
            sh_d0[w][2 + k1][n] = wig[(size_t)eb * 256 + n];
        }
        __syncwarp();

        // ---- rotation: u = D0 @ x (both endpoints) ----
        const int half = lane >> 4;
        const int li   = lane & 15;
#pragma unroll
        for (int k = 0; k < 4; k++) {
            const float4* xs4 = (const float4*)(x + (size_t)s[k] * 1024);
            const float4* xt4 = (const float4*)(x + (size_t)d[k] * 1024);
            float4 as = make_float4(0.f, 0.f, 0.f, 0.f);
            float4 at = make_float4(0.f, 0.f, 0.f, 0.f);
#pragma unroll
            for (int i = 0; i < 8; i++) {
                int row = 2 * i + half;
                float dn = sh_d0[w][k][row];
                float4 a = xs4[row * 16 + li];
                float4 b = xt4[row * 16 + li];
                as.x += dn * a.x; as.y += dn * a.y; as.z += dn * a.z; as.w += dn * a.w;
                at.x += dn * b.x; at.y += dn * b.y; at.z += dn * b.z; at.w += dn * b.w;
            }
            as.x += __shfl_xor_sync(0xffffffffu, as.x, 16);
            as.y += __shfl_xor_sync(0xffffffffu, as.y, 16);
            as.z += __shfl_xor_sync(0xffffffffu, as.z, 16);
            as.w += __shfl_xor_sync(0xffffffffu, as.w, 16);
            at.x += __shfl_xor_sync(0xffffffffu, at.x, 16);
            at.y += __shfl_xor_sync(0xffffffffu, at.y, 16);
            at.z += __shfl_xor_sync(0xffffffffu, at.z, 16);
            at.w += __shfl_xor_sync(0xffffffffu, at.w, 16);
            float4 v = half ? at : as;
            float* dst = half ? &sh_ut[w][k][4 * li] : &sh_us[w][k][4 * li];
            *(float4*)dst = v;
        }

        // ---- edge scalar embedding ----
        float wdl = wd[lane];
#pragma unroll
        for (int k = 0; k < 4; k++) {
            int zs = zn[s[k]], zd = zn[d[k]];
            float dd = dist[eid[k]];
            float ev = silu_f(dd * wdl + emb_s[zs * CEDIM + lane] + emb_t[zd * CEDIM + lane]);
            sh_e[w][k][lane] = ev;
            if ((vmask >> k) & 1) g_e[(size_t)eid[k] * CEDIM + lane] = ev;
        }
        __syncwarp();

        // ---- mix: f0[h] = sum_c us[c]*WsT[h][c] + ut[c]*WtT[h][c] ----
        float2 f0[4];
#pragma unroll
        for (int k = 0; k < 4; k++) f0[k] = make_float2(0.f, 0.f);
        {
            const float4* wsr0 = (const float4*)(g_WsT[bv] + (2 * lane) * CDIM);
            const float4* wsr1 = wsr0 + (CDIM / 4);
            const float4* wtr0 = (const float4*)(g_WtT[bv] + (2 * lane) * CDIM);
            const float4* wtr1 = wtr0 + (CDIM / 4);
#pragma unroll 4
            for (int c4 = 0; c4 < 16; c4++) {
                float4 ws0 = wsr0[c4], ws1 = wsr1[c4];
                float4 wt0 = wtr0[c4], wt1 = wtr1[c4];
#pragma unroll
                for (int k = 0; k < 4; k++) {
                    float4 u = *(const float4*)&sh_us[w][k][4 * c4];
                    float4 t = *(const float4*)&sh_ut[w][k][4 * c4];
                    f0[k].x += u.x * ws0.x + u.y * ws0.y + u.z * ws0.z + u.w * ws0.w
                             + t.x * wt0.x + t.y * wt0.y + t.z * wt0.z + t.w * wt0.w;
                    f0[k].y += u.x * ws1.x + u.y * ws1.y + u.z * ws1.z + u.w * ws1.w
                             + t.x * wt1.x + t.y * wt1.y + t.z * wt1.z + t.w * wt1.w;
                }
            }
        }
        // ---- + e @ We ----
        {
            const float4* wer0 = (const float4*)(g_WeT[bv] + (2 * lane) * CEDIM);
            const float4* wer1 = wer0 + (CEDIM / 4);
#pragma unroll
            for (int c4 = 0; c4 < 8; c4++) {
                float4 we0 = wer0[c4], we1 = wer1[c4];
#pragma unroll
                for (int k = 0; k < 4; k++) {
                    float4 ev = *(const float4*)&sh_e[w][k][4 * c4];
                    f0[k].x += ev.x * we0.x + ev.y * we0.y + ev.z * we0.z + ev.w * we0.w;
                    f0[k].y += ev.x * we1.x + ev.y * we1.y + ev.z * we1.z + ev.w * we1.w;
                }
            }
        }
#pragma unroll
        for (int k = 0; k < 4; k++)
            *(float2*)&sh_f0[w][k][2 * lane] = f0[k];
        __syncwarp();

        // ---- alpha features: acc[o] = sum_h f0[h]*WaT[o][h], lrelu, *va ----
        float2 acc[4];
#pragma unroll
        for (int k = 0; k < 4; k++) acc[k] = make_float2(0.f, 0.f);
        {
            const float4* war0 = (const float4*)(g_WaT[bv] + (2 * lane) * HDIM);
            const float4* war1 = war0 + (HDIM / 4);
#pragma unroll 4
            for (int h4 = 0; h4 < 16; h4++) {
                float4 a0 = war0[h4], a1 = war1[h4];
#pragma unroll
                for (int k = 0; k < 4; k++) {
                    float4 fv = *(const float4*)&sh_f0[w][k][4 * h4];
                    acc[k].x += fv.x * a0.x + fv.y * a0.y + fv.z * a0.z + fv.w * a0.w;
                    acc[k].y += fv.x * a1.x + fv.y * a1.y + fv.z * a1.z + fv.w * a1.w;
                }
            }
        }
        float vax = va[2 * lane], vay = va[2 * lane + 1];
        float sr[4];
#pragma unroll
        for (int k = 0; k < 4; k++) {
            float ax = acc[k].x > 0.f ? acc[k].x : 0.2f * acc[k].x;
            float ay = acc[k].y > 0.f ? acc[k].y : 0.2f * acc[k].y;
            float sv = ax * vax + ay * vay;
            sv += __shfl_xor_sync(0xffffffffu, sv, 1);
            sv += __shfl_xor_sync(0xffffffffu, sv, 2);
            sr[k] = sv;   // lanes 4h..4h+3 all hold head-h logit of edge k
        }

        // ---- write exp + segment sum: lane -> (edge kk, head hh) ----
        int kk = lane & 3, hh = lane >> 2;
        if ((vmask >> kk) & 1) {
            float sv = self4(kk, sr[0], sr[1], sr[2], sr[3]);
            int ed   = seli4(kk, eid[0], eid[1], eid[2], eid[3]);
            int dd   = seli4(kk, d[0], d[1], d[2], d[3]);
            float ex = expf(sv);
            g_ex[(size_t)ed * NHEADS + hh] = ex;
            atomicAdd(&g_segsum[dd * NHEADS + hh], ex);
        }
    };

    if (base + 4 <= cnt0)      process(0, 0xF);
    else if (base >= cnt0)     process(1, 0xF);
    else {
        int m0 = (1 << (cnt0 - base)) - 1;
        process(0, m0);
        process(1, 0xF ^ m0);
    }
}

// ---------------------------------------------------------------------------
// K2: output contributions.  One warp per 4 edges.
// c[e,j] = x_s[j,:].(Ws q) + x_t[j,:].(Wt q) + D0[j].(e.(We q)), j=1..3
// ---------------------------------------------------------------------------
__global__ void __launch_bounds__(256)
pass2_kernel(
    const float* __restrict__ x, const int* __restrict__ eidx,
    const float* __restrict__ wig,
    float* __restrict__ out)
{
    __shared__ __align__(16) float sh_q [8][4][HDIM];
    __shared__ float sh_al[8][4][NHEADS];

    const int w    = threadIdx.x >> 5;
    const int lane = threadIdx.x & 31;
    const int g    = blockIdx.x * 8 + w;
    const int base = g * 4;
    const int cnt0 = g_cnt[0];

    int eid[4], s[4], d[4];
#pragma unroll
    for (int k = 0; k < 4; k++) {
        eid[k] = g_order[base + k];
        s[k]   = eidx[eid[k]];
        d[k]   = eidx[NE + eid[k]];
    }

    auto process = [&](int bv, int vmask) {
        // ---- alpha for all 4 edges: lane -> (edge kk, head hh) ----
        {
            int kk = lane & 3, hh = lane >> 2;
            int ed = seli4(kk, eid[0], eid[1], eid[2], eid[3]);
            int dd = seli4(kk, d[0], d[1], d[2], d[3]);
            float ex = g_ex[(size_t)ed * NHEADS + hh];
            sh_al[w][kk][hh] = ex / (g_segsum[dd * NHEADS + hh] + 1e-9f);
        }
        __syncwarp();

        // ---- q = P @ alpha  (lane owns hidden pair) ----
        float2 q[4];
#pragma unroll
        for (int k = 0; k < 4; k++) q[k] = make_float2(0.f, 0.f);
#pragma unroll
        for (int head = 0; head < NHEADS; head++) {
            float2 p = *(const float2*)&g_PT[bv][head * HDIM + 2 * lane];
#pragma unroll
            for (int k = 0; k < 4; k++) {
                float al = sh_al[w][k][head];
                q[k].x += al * p.x;
                q[k].y += al * p.y;
            }
        }
#pragma unroll
        for (int k = 0; k < 4; k++)
            *(float2*)&sh_q[w][k][2 * lane] = q[k];
        __syncwarp();

        // ---- rs = Ws@q, rt = Wt@q, wq = We@q ----
        float2 rs[4], rt[4]; float wq[4];
#pragma unroll
        for (int k = 0; k < 4; k++) { rs[k] = make_float2(0.f, 0.f); rt[k] = make_float2(0.f, 0.f); wq[k] = 0.f; }
#pragma unroll 8
        for (int h = 0; h < HDIM; h++) {
            float2 a = *(const float2*)&g_WsT[bv][h * CDIM + 2 * lane];
            float2 b = *(const float2*)&g_WtT[bv][h * CDIM + 2 * lane];
            float wv = g_WeT[bv][h * CEDIM + lane];
#pragma unroll
            for (int k = 0; k < 4; k++) {
                float qh = sh_q[w][k][h];
                rs[k].x += qh * a.x; rs[k].y += qh * a.y;
                rt[k].x += qh * b.x; rt[k].y += qh * b.y;
                wq[k]   += qh * wv;
            }
        }

        // ---- per-edge: embedding term + x rows 1..3, reduce, scatter ----
#pragma unroll
        for (int k = 0; k < 4; k++) {
            float ev = g_e[(size_t)eid[k] * CEDIM + lane];
            float tp = ev * wq[k];

            const float2* xs2 = (const float2*)(x + (size_t)s[k] * 1024);
            const float2* xt2 = (const float2*)(x + (size_t)d[k] * 1024);
            float2 a1 = xs2[1 * 32 + lane], b1 = xt2[1 * 32 + lane];
            float p1 = a1.x * rs[k].x + a1.y * rs[k].y + b1.x * rt[k].x + b1.y * rt[k].y;
            float2 a2 = xs2[2 * 32 + lane], b2 = xt2[2 * 32 + lane];
            float p2 = a2.x * rs[k].x + a2.y * rs[k].y + b2.x * rt[k].x + b2.y * rt[k].y;
            float2 a3 = xs2[3 * 32 + lane], b3 = xt2[3 * 32 + lane];
            float p3 = a3.x * rs[k].x + a3.y * rs[k].y + b3.x * rt[k].x + b3.y * rt[k].y;

#pragma unroll
            for (int off = 16; off >= 1; off >>= 1) {
                tp += __shfl_down_sync(0xffffffffu, tp, off);
                p1 += __shfl_down_sync(0xffffffffu, p1, off);
                p2 += __shfl_down_sync(0xffffffffu, p2, off);
                p3 += __shfl_down_sync(0xffffffffu, p3, off);
            }

            if (lane == 0 && ((vmask >> k) & 1)) {
                float d01 = wig[(size_t)eid[k] * 256 + 1];
                float d02 = wig[(size_t)eid[k] * 256 + 2];
                float d03 = wig[(size_t)eid[k] * 256 + 3];
                atomicAdd(&out[d[k] * 3 + 0], p1 + d01 * tp);
                atomicAdd(&out[d[k] * 3 + 1], p2 + d02 * tp);
                atomicAdd(&out[d[k] * 3 + 2], p3 + d03 * tp);
            }
        }
    };

    if (base + 4 <= cnt0)      process(0, 0xF);
    else if (base >= cnt0)     process(1, 0xF);
    else {
        int m0 = (1 << (cnt0 - base)) - 1;
        process(0, m0);
        process(1, 0xF ^ m0);
    }
}

// ---------------------------------------------------------------------------
extern "C" void kernel_launch(void* const* d_in, const int* in_sizes, int n_in,
                              void* d_out, int out_size)
{
    const float* x    = (const float*)d_in[0];
    const int*   zn   = (const int*)d_in[1];
    const float* dist = (const float*)d_in[2];
    const int*   eidx = (const int*)d_in[3];
    const int*   mask = (const int*)d_in[4];
    const float* wig  = (const float*)d_in[5];

    const float* fs_emb_s = (const float*)d_in[6];
    const float* fs_emb_t = (const float*)d_in[7];
    const float* fs_wd    = (const float*)d_in[8];
    const float* fs_We    = (const float*)d_in[9];
    const float* fs_Ws    = (const float*)d_in[10];
    const float* fs_Wt    = (const float*)d_in[11];
    const float* fs_Wa    = (const float*)d_in[12];
    const float* fs_va    = (const float*)d_in[13];
    const float* fs_Wv    = (const float*)d_in[14];
    const float* fs_Wo    = (const float*)d_in[15];

    const float* dn_emb_s = (const float*)d_in[16];
    const float* dn_emb_t = (const float*)d_in[17];
    const float* dn_wd    = (const float*)d_in[18];
    const float* dn_We    = (const float*)d_in[19];
    const float* dn_Ws    = (const float*)d_in[20];
    const float* dn_Wt    = (const float*)d_in[21];
    const float* dn_Wa    = (const float*)d_in[22];
    const float* dn_va    = (const float*)d_in[23];
    const float* dn_Wv    = (const float*)d_in[24];
    const float* dn_Wo    = (const float*)d_in[25];

    float* out = (float*)d_out;

    setup_kernel<<<64, 256>>>(fs_We, fs_Ws, fs_Wt, fs_Wa, fs_Wv, fs_Wo,
                              dn_We, dn_Ws, dn_Wt, dn_Wa, dn_Wv, dn_Wo, out);

    bucket_kernel<<<(NE + 255) / 256, 256>>>(eidx, mask);

    // 15000 groups of 4 edges, 8 warps/block -> 1875 blocks exactly
    pass1_kernel<<<1875, 256>>>(x, zn, dist, eidx, wig,
                                fs_emb_s, fs_emb_t, fs_wd, fs_va,
                                dn_emb_s, dn_emb_t, dn_wd, dn_va);

    pass2_kernel<<<1875, 256>>>(x, eidx, wig, out);
}

// round 6
// speedup vs baseline: 2.0273x; 2.0273x over previous
#include <cuda_runtime.h>
#include <math.h>

#define NN 4000
#define NE 60000
#define MDIM 16
#define CDIM 64
#define HDIM 64
#define NHEADS 8
#define ADIM 8
#define VCDIM 8
#define CEDIM 32
#define NROWS (NN * MDIM)          // 64000 rows of x viewed as [64000, 64]

// ---- scratch (__device__ globals: no allocation allowed) ----
__device__ float g_G[4][(size_t)NROWS * HDIM]; // 0:fs_Ws 1:fs_Wt 2:dn_Ws 3:dn_Wt  (x @ W per node-row)
__device__ float g_ew[(size_t)NE * HDIM];      // e @ We per edge (pass1 -> pass2)
__device__ float g_ex[NE * NHEADS];            // exp(logits)
__device__ float g_segsum[NN * NHEADS];        // softmax denominators
__device__ int   g_cnt[2];
__device__ int   g_order[NE];                  // edge ids partitioned by blk
__device__ float g_PT[2][NHEADS * HDIM];       // PT[head*64+c] = sum_vc Wv[c,head*8+vc]*Wo[head*8+vc]

__device__ __forceinline__ float silu_f(float v) { return v / (1.0f + __expf(-v)); }

// ---------------------------------------------------------------------------
// K0: zero accumulators + build PT
// ---------------------------------------------------------------------------
__global__ void setup_kernel(
    const float* __restrict__ fs_Wv, const float* __restrict__ fs_Wo,
    const float* __restrict__ dn_Wv, const float* __restrict__ dn_Wo,
    float* __restrict__ out)
{
    int tid = blockIdx.x * blockDim.x + threadIdx.x;
    int nt  = gridDim.x * blockDim.x;

    if (tid < 2) g_cnt[tid] = 0;
    for (int i = tid; i < NN * 3; i += nt) out[i] = 0.0f;
    for (int i = tid; i < NN * NHEADS; i += nt) g_segsum[i] = 0.0f;

    for (int i = tid; i < 2 * NHEADS * HDIM; i += nt) {
        int blk = i >> 9; int r = i & 511;
        int h = r >> 6; int c = r & 63;
        const float* Wv = blk ? dn_Wv : fs_Wv;
        const float* Wo = blk ? dn_Wo : fs_Wo;
        float acc = 0.0f;
#pragma unroll
        for (int vc = 0; vc < VCDIM; vc++)
            acc += Wv[c * (NHEADS * VCDIM) + h * VCDIM + vc] * Wo[h * VCDIM + vc];
        g_PT[blk][h * HDIM + c] = acc;
    }
}

// ---------------------------------------------------------------------------
// K0b: bucket edges by blk = mask[dst]
// ---------------------------------------------------------------------------
__global__ void bucket_kernel(const int* __restrict__ eidx, const int* __restrict__ mask)
{
    int e = blockIdx.x * blockDim.x + threadIdx.x;
    bool valid = e < NE;
    int b = 0;
    if (valid) b = (mask[eidx[NE + e]] != 0) ? 1 : 0;
    unsigned m1 = __ballot_sync(0xffffffffu, valid && (b == 1));
    unsigned m0 = __ballot_sync(0xffffffffu, valid && (b == 0));
    int lane = threadIdx.x & 31;
    int base0 = 0, base1 = 0;
    if (lane == 0) {
        int n0 = __popc(m0), n1 = __popc(m1);
        if (n0) base0 = atomicAdd(&g_cnt[0], n0);
        if (n1) base1 = atomicAdd(&g_cnt[1], n1);
    }
    base0 = __shfl_sync(0xffffffffu, base0, 0);
    base1 = __shfl_sync(0xffffffffu, base1, 0);
    unsigned lt = (1u << lane) - 1u;
    if (valid) {
        int pos;
        if (b) pos = NE - 1 - (base1 + __popc(m1 & lt));
        else   pos = base0 + __popc(m0 & lt);
        g_order[pos] = e;
    }
}

// ---------------------------------------------------------------------------
// K0c: G tables.  C[64000,64] = X[64000,64] @ W[64,64] for 4 weight matrices.
// CTA: 64 rows x 64 cols, 128 threads, thread tile 8x4, packed f32x2 FMA.
// ---------------------------------------------------------------------------
__global__ void __launch_bounds__(128)
mm_kernel(const float* __restrict__ x,
          const float* __restrict__ fs_Ws, const float* __restrict__ fs_Wt,
          const float* __restrict__ dn_Ws, const float* __restrict__ dn_Wt)
{
    __shared__ float Xs[64][65];
    __shared__ float Wsm[64][64];

    const int m = blockIdx.y;
    const float* W = (m == 0) ? fs_Ws : (m == 1) ? fs_Wt : (m == 2) ? dn_Ws : dn_Wt;
    const int row0 = blockIdx.x * 64;
    const int tid  = threadIdx.x;

    // load X tile (64x64) and W (64x64)
#pragma unroll
    for (int i = 0; i < 8; i++) {
        int f4 = i * 128 + tid;            // 0..1023
        int r = f4 >> 4, c4 = (f4 & 15) * 4;
        float4 v = *(const float4*)(x + (size_t)(row0 + r) * 64 + c4);
        Xs[r][c4] = v.x; Xs[r][c4 + 1] = v.y; Xs[r][c4 + 2] = v.z; Xs[r][c4 + 3] = v.w;
        *(float4*)&Wsm[r][c4] = *(const float4*)(W + r * 64 + c4);
    }
    __syncthreads();

    const int tc = tid & 15, tr = tid >> 4;
    const int c0 = tc * 4, r0 = tr * 8;

    unsigned long long acc[8][2];
#pragma unroll
    for (int i = 0; i < 8; i++) { acc[i][0] = 0ull; acc[i][1] = 0ull; }

#pragma unroll 4
    for (int k = 0; k < 64; k++) {
        unsigned long long b0 = *(const unsigned long long*)&Wsm[k][c0];
        unsigned long long b1 = *(const unsigned long long*)&Wsm[k][c0 + 2];
#pragma unroll
        for (int i = 0; i < 8; i++) {
            float a = Xs[r0 + i][k];
            unsigned long long aa;
            asm("mov.b64 %0, {%1, %1};" : "=l"(aa) : "f"(a));
            asm("fma.rn.f32x2 %0, %1, %2, %0;" : "+l"(acc[i][0]) : "l"(aa), "l"(b0));
            asm("fma.rn.f32x2 %0, %1, %2, %0;" : "+l"(acc[i][1]) : "l"(aa), "l"(b1));
        }
    }

    float* outp = g_G[m];
#pragma unroll
    for (int i = 0; i < 8; i++) {
        float2 p0 = *(float2*)&acc[i][0];
        float2 p1 = *(float2*)&acc[i][1];
        float4 v = make_float4(p0.x, p0.y, p1.x, p1.y);
        *(float4*)(outp + (size_t)(row0 + r0 + i) * 64 + c0) = v;
    }
}

// ---------------------------------------------------------------------------
// K1: logits + exp + segment sum.  One warp per edge.
// f0[h] = sum_n D0[n] * (GS[s][n][h] + GT[d][n][h]) + (e@We)[h]
// ---------------------------------------------------------------------------
__global__ void __launch_bounds__(256)
pass1_kernel(
    const int* __restrict__ zn,
    const float* __restrict__ dist, const int* __restrict__ eidx,
    const float* __restrict__ wig,
    const float* __restrict__ fs_emb_s, const float* __restrict__ fs_emb_t,
    const float* __restrict__ fs_wd, const float* __restrict__ fs_We,
    const float* __restrict__ fs_Wa, const float* __restrict__ fs_va,
    const float* __restrict__ dn_emb_s, const float* __restrict__ dn_emb_t,
    const float* __restrict__ dn_wd, const float* __restrict__ dn_We,
    const float* __restrict__ dn_Wa, const float* __restrict__ dn_va)
{
    __shared__ float sh_d0[8][MDIM];
    __shared__ float sh_e [8][CEDIM];
    __shared__ float sh_f0[8][HDIM];
    __shared__ float sh_av[8][HDIM];

    const int w    = threadIdx.x >> 5;
    const int lane = threadIdx.x & 31;
    const int pos  = blockIdx.x * 8 + w;
    if (pos >= NE) return;

    const int ed  = g_order[pos];
    const int s   = eidx[ed];
    const int d   = eidx[NE + ed];
    const int blk = (pos >= g_cnt[0]) ? 1 : 0;

    const float* emb_s = blk ? dn_emb_s : fs_emb_s;
    const float* emb_t = blk ? dn_emb_t : fs_emb_t;
    const float* wd    = blk ? dn_wd    : fs_wd;
    const float* We    = blk ? dn_We    : fs_We;
    const float* Wa    = blk ? dn_Wa    : fs_Wa;
    const float* va    = blk ? dn_va    : fs_va;

    if (lane < MDIM) sh_d0[w][lane] = wig[(size_t)ed * 256 + lane];
    __syncwarp();

    // ---- f0 from G tables (lane owns h = 2*lane, 2*lane+1) ----
    const float* GSb = g_G[2 * blk]     + (size_t)s * (MDIM * HDIM);
    const float* GTb = g_G[2 * blk + 1] + (size_t)d * (MDIM * HDIM);
    float2 f0 = make_float2(0.f, 0.f);
#pragma unroll
    for (int n = 0; n < MDIM; n++) {
        float dn = sh_d0[w][n];
        float2 a = *(const float2*)(GSb + n * HDIM + 2 * lane);
        float2 b = *(const float2*)(GTb + n * HDIM + 2 * lane);
        f0.x += dn * (a.x + b.x);
        f0.y += dn * (a.y + b.y);
    }

    // ---- edge scalar embedding (CE=32, one per lane) ----
    {
        int zs = zn[s], zd = zn[d];
        float dd = dist[ed];
        float ev = dd * wd[lane] + emb_s[zs * CEDIM + lane] + emb_t[zd * CEDIM + lane];
        sh_e[w][lane] = silu_f(ev);
    }
    __syncwarp();

    // ---- ew = e @ We ; save for pass2 ; f0 += ew ----
    {
        float2 ew = make_float2(0.f, 0.f);
#pragma unroll 8
        for (int ce = 0; ce < CEDIM; ce++) {
            float ev = sh_e[w][ce];
            float2 w2 = *(const float2*)(We + ce * HDIM + 2 * lane);
            ew.x += ev * w2.x; ew.y += ev * w2.y;
        }
        *(float2*)(g_ew + (size_t)ed * HDIM + 2 * lane) = ew;
        f0.x += ew.x; f0.y += ew.y;
    }
    *(float2*)&sh_f0[w][2 * lane] = f0;
    __syncwarp();

    // ---- alpha features: acc[o] = sum_h f0[h]*Wa[h][o], lrelu, *va ----
    {
        float2 acc = make_float2(0.f, 0.f);
#pragma unroll 8
        for (int h = 0; h < HDIM; h++) {
            float fh = sh_f0[w][h];
            float2 wa = *(const float2*)(Wa + h * (NHEADS * ADIM) + 2 * lane);
            acc.x += fh * wa.x; acc.y += fh * wa.y;
        }
        acc.x = acc.x > 0.f ? acc.x : 0.2f * acc.x;
        acc.y = acc.y > 0.f ? acc.y : 0.2f * acc.y;
        float2 vv = *(const float2*)(va + 2 * lane);
        sh_av[w][2 * lane]     = acc.x * vv.x;
        sh_av[w][2 * lane + 1] = acc.y * vv.y;
    }
    __syncwarp();

    if (lane < NHEADS) {
        float lg = 0.f;
#pragma unroll
        for (int a = 0; a < ADIM; a++) lg += sh_av[w][lane * ADIM + a];
        float ex = expf(lg);
        g_ex[(size_t)ed * NHEADS + lane] = ex;
        atomicAdd(&g_segsum[d * NHEADS + lane], ex);
    }
}

// ---------------------------------------------------------------------------
// K2: output contributions.  One warp per edge.
// p_j = q . (GS[s][j] + GT[d][j])  (j=1..3),  tpart = q . ew[e]
// out[d][j] += p_j + D0[j] * tpart
// ---------------------------------------------------------------------------
__global__ void __launch_bounds__(256)
pass2_kernel(const int* __restrict__ eidx, const float* __restrict__ wig,
             float* __restrict__ out)
{
    __shared__ float sh_al[8][NHEADS];

    const int w    = threadIdx.x >> 5;
    const int lane = threadIdx.x & 31;
    const int pos  = blockIdx.x * 8 + w;
    if (pos >= NE) return;

    const int ed  = g_order[pos];
    const int s   = eidx[ed];
    const int d   = eidx[NE + ed];
    const int blk = (pos >= g_cnt[0]) ? 1 : 0;

    if (lane < NHEADS) {
        float ex = g_ex[(size_t)ed * NHEADS + lane];
        sh_al[w][lane] = ex / (g_segsum[d * NHEADS + lane] + 1e-9f);
    }
    __syncwarp();

    // q = P @ alpha (lane owns h pair)
    float2 q = make_float2(0.f, 0.f);
#pragma unroll
    for (int head = 0; head < NHEADS; head++) {
        float al = sh_al[w][head];
        float2 p = *(const float2*)&g_PT[blk][head * HDIM + 2 * lane];
        q.x += al * p.x; q.y += al * p.y;
    }

    const float* GSb = g_G[2 * blk]     + (size_t)s * (MDIM * HDIM);
    const float* GTb = g_G[2 * blk + 1] + (size_t)d * (MDIM * HDIM);

    float2 a1 = *(const float2*)(GSb + 1 * HDIM + 2 * lane);
    float2 b1 = *(const float2*)(GTb + 1 * HDIM + 2 * lane);
    float2 a2 = *(const float2*)(GSb + 2 * HDIM + 2 * lane);
    float2 b2 = *(const float2*)(GTb + 2 * HDIM + 2 * lane);
    float2 a3 = *(const float2*)(GSb + 3 * HDIM + 2 * lane);
    float2 b3 = *(const float2*)(GTb + 3 * HDIM + 2 * lane);
    float2 ew = *(const float2*)(g_ew + (size_t)ed * HDIM + 2 * lane);

    float p1 = q.x * (a1.x + b1.x) + q.y * (a1.y + b1.y);
    float p2 = q.x * (a2.x + b2.x) + q.y * (a2.y + b2.y);
    float p3 = q.x * (a3.x + b3.x) + q.y * (a3.y + b3.y);
    float tp = q.x * ew.x + q.y * ew.y;

#pragma unroll
    for (int off = 16; off >= 1; off >>= 1) {
        p1 += __shfl_down_sync(0xffffffffu, p1, off);
        p2 += __shfl_down_sync(0xffffffffu, p2, off);
        p3 += __shfl_down_sync(0xffffffffu, p3, off);
        tp += __shfl_down_sync(0xffffffffu, tp, off);
    }

    if (lane == 0) {
        float4 w0 = *(const float4*)(wig + (size_t)ed * 256);  // D0[0..3]
        atomicAdd(&out[d * 3 + 0], p1 + w0.y * tp);
        atomicAdd(&out[d * 3 + 1], p2 + w0.z * tp);
        atomicAdd(&out[d * 3 + 2], p3 + w0.w * tp);
    }
}

// ---------------------------------------------------------------------------
extern "C" void kernel_launch(void* const* d_in, const int* in_sizes, int n_in,
                              void* d_out, int out_size)
{
    const float* x    = (const float*)d_in[0];
    const int*   zn   = (const int*)d_in[1];
    const float* dist = (const float*)d_in[2];
    const int*   eidx = (const int*)d_in[3];
    const int*   mask = (const int*)d_in[4];
    const float* wig  = (const float*)d_in[5];

    const float* fs_emb_s = (const float*)d_in[6];
    const float* fs_emb_t = (const float*)d_in[7];
    const float* fs_wd    = (const float*)d_in[8];
    const float* fs_We    = (const float*)d_in[9];
    const float* fs_Ws    = (const float*)d_in[10];
    const float* fs_Wt    = (const float*)d_in[11];
    const float* fs_Wa    = (const float*)d_in[12];
    const float* fs_va    = (const float*)d_in[13];
    const float* fs_Wv    = (const float*)d_in[14];
    const float* fs_Wo    = (const float*)d_in[15];

    const float* dn_emb_s = (const float*)d_in[16];
    const float* dn_emb_t = (const float*)d_in[17];
    const float* dn_wd    = (const float*)d_in[18];
    const float* dn_We    = (const float*)d_in[19];
    const float* dn_Ws    = (const float*)d_in[20];
    const float* dn_Wt    = (const float*)d_in[21];
    const float* dn_Wa    = (const float*)d_in[22];
    const float* dn_va    = (const float*)d_in[23];
    const float* dn_Wv    = (const float*)d_in[24];
    const float* dn_Wo    = (const float*)d_in[25];

    float* out = (float*)d_out;

    setup_kernel<<<32, 256>>>(fs_Wv, fs_Wo, dn_Wv, dn_Wo, out);

    bucket_kernel<<<(NE + 255) / 256, 256>>>(eidx, mask);

    mm_kernel<<<dim3(NROWS / 64, 4), 128>>>(x, fs_Ws, fs_Wt, dn_Ws, dn_Wt);

    // one warp per edge: 60000 warps = 7500 blocks x 8 warps
    pass1_kernel<<<7500, 256>>>(zn, dist, eidx, wig,
                                fs_emb_s, fs_emb_t, fs_wd, fs_We, fs_Wa, fs_va,
                                dn_emb_s, dn_emb_t, dn_wd, dn_We, dn_Wa, dn_va);

    pass2_kernel<<<7500, 256>>>(eidx, wig, out);
}

// round 11
// speedup vs baseline: 2.1955x; 1.0830x over previous
#include <cuda_runtime.h>
#include <math.h>

#define NN 4000
#define NE 60000
#define MDIM 16
#define CDIM 64
#define HDIM 64
#define NHEADS 8
#define ADIM 8
#define VCDIM 8
#define CEDIM 32
#define NROWS (NN * MDIM)          // 64000 rows of x viewed as [64000, 64]
#define EPC 64                     // edges per CTA in pass1

// ---- scratch (__device__ globals: no allocation allowed) ----
__device__ float g_G[4][(size_t)NROWS * HDIM]; // 0:fs_Ws 1:fs_Wt 2:dn_Ws 3:dn_Wt
__device__ float g_ew[(size_t)NE * HDIM];      // (e @ We) per bucketed position
__device__ float g_ex[NE * NHEADS];            // exp(logits) per bucketed position
__device__ float g_segsum[NN * NHEADS];        // softmax denominators
__device__ int   g_cnt[2];
__device__ int   g_order[NE];                  // edge ids partitioned by blk
__device__ float g_PT[2][NHEADS * HDIM];       // PT[head*64+c] = sum_vc Wv[c,head*8+vc]*Wo[head*8+vc]

__device__ __forceinline__ float silu_f(float v) { return v / (1.0f + __expf(-v)); }

// ---------------------------------------------------------------------------
// K0: zero accumulators + build PT
// ---------------------------------------------------------------------------
__global__ void setup_kernel(
    const float* __restrict__ fs_Wv, const float* __restrict__ fs_Wo,
    const float* __restrict__ dn_Wv, const float* __restrict__ dn_Wo,
    float* __restrict__ out)
{
    int tid = blockIdx.x * blockDim.x + threadIdx.x;
    int nt  = gridDim.x * blockDim.x;

    if (tid < 2) g_cnt[tid] = 0;
    for (int i = tid; i < NN * 3; i += nt) out[i] = 0.0f;
    for (int i = tid; i < NN * NHEADS; i += nt) g_segsum[i] = 0.0f;

    for (int i = tid; i < 2 * NHEADS * HDIM; i += nt) {
        int blk = i >> 9; int r = i & 511;
        int h = r >> 6; int c = r & 63;
        const float* Wv = blk ? dn_Wv : fs_Wv;
        const float* Wo = blk ? dn_Wo : fs_Wo;
        float acc = 0.0f;
#pragma unroll
        for (int vc = 0; vc < VCDIM; vc++)
            acc += Wv[c * (NHEADS * VCDIM) + h * VCDIM + vc] * Wo[h * VCDIM + vc];
        g_PT[blk][h * HDIM + c] = acc;
    }
}

// ---------------------------------------------------------------------------
// K0b: bucket edges by blk = mask[dst]
// ---------------------------------------------------------------------------
__global__ void bucket_kernel(const int* __restrict__ eidx, const int* __restrict__ mask)
{
    int e = blockIdx.x * blockDim.x + threadIdx.x;
    bool valid = e < NE;
    int b = 0;
    if (valid) b = (mask[eidx[NE + e]] != 0) ? 1 : 0;
    unsigned m1 = __ballot_sync(0xffffffffu, valid && (b == 1));
    unsigned m0 = __ballot_sync(0xffffffffu, valid && (b == 0));
    int lane = threadIdx.x & 31;
    int base0 = 0, base1 = 0;
    if (lane == 0) {
        int n0 = __popc(m0), n1 = __popc(m1);
        if (n0) base0 = atomicAdd(&g_cnt[0], n0);
        if (n1) base1 = atomicAdd(&g_cnt[1], n1);
    }
    base0 = __shfl_sync(0xffffffffu, base0, 0);
    base1 = __shfl_sync(0xffffffffu, base1, 0);
    unsigned lt = (1u << lane) - 1u;
    if (valid) {
        int pos;
        if (b) pos = NE - 1 - (base1 + __popc(m1 & lt));
        else   pos = base0 + __popc(m0 & lt);
        g_order[pos] = e;
    }
}

// ---------------------------------------------------------------------------
// K0c: G tables.  C[64000,64] = X[64000,64] @ W[64,64] for 4 weight matrices.
// ---------------------------------------------------------------------------
__global__ void __launch_bounds__(128)
mm_kernel(const float* __restrict__ x,
          const float* __restrict__ fs_Ws, const float* __restrict__ fs_Wt,
          const float* __restrict__ dn_Ws, const float* __restrict__ dn_Wt)
{
    __shared__ float Xs[64][65];
    __shared__ float Wsm[64][64];

    const int m = blockIdx.y;
    const float* W = (m == 0) ? fs_Ws : (m == 1) ? fs_Wt : (m == 2) ? dn_Ws : dn_Wt;
    const int row0 = blockIdx.x * 64;
    const int tid  = threadIdx.x;

#pragma unroll
    for (int i = 0; i < 8; i++) {
        int f4 = i * 128 + tid;
        int r = f4 >> 4, c4 = (f4 & 15) * 4;
        float4 v = *(const float4*)(x + (size_t)(row0 + r) * 64 + c4);
        Xs[r][c4] = v.x; Xs[r][c4 + 1] = v.y; Xs[r][c4 + 2] = v.z; Xs[r][c4 + 3] = v.w;
        *(float4*)&Wsm[r][c4] = *(const float4*)(W + r * 64 + c4);
    }
    __syncthreads();

    const int tc = tid & 15, tr = tid >> 4;
    const int c0 = tc * 4, r0 = tr * 8;

    unsigned long long acc[8][2];
#pragma unroll
    for (int i = 0; i < 8; i++) { acc[i][0] = 0ull; acc[i][1] = 0ull; }

#pragma unroll 4
    for (int k = 0; k < 64; k++) {
        unsigned long long b0 = *(const unsigned long long*)&Wsm[k][c0];
        unsigned long long b1 = *(const unsigned long long*)&Wsm[k][c0 + 2];
#pragma unroll
        for (int i = 0; i < 8; i++) {
            float a = Xs[r0 + i][k];
            unsigned long long aa;
            asm("mov.b64 %0, {%1, %1};" : "=l"(aa) : "f"(a));
            asm("fma.rn.f32x2 %0, %1, %2, %0;" : "+l"(acc[i][0]) : "l"(aa), "l"(b0));
            asm("fma.rn.f32x2 %0, %1, %2, %0;" : "+l"(acc[i][1]) : "l"(aa), "l"(b1));
        }
    }

    float* outp = g_G[m];
#pragma unroll
    for (int i = 0; i < 8; i++) {
        float2 p0 = *(float2*)&acc[i][0];
        float2 p1 = *(float2*)&acc[i][1];
        float4 v = make_float4(p0.x, p0.y, p1.x, p1.y);
        *(float4*)(outp + (size_t)(row0 + r0 + i) * 64 + c0) = v;
    }
}

// ---------------------------------------------------------------------------
// K1: batched pass1.  One CTA per 64 bucketed positions.
//   A) per-warp: Fp[e][h] = sum_n D0[n]*(GS[s][n][h]+GT[d][n][h]); E[e][ce]
//   B) EW = E @ We (smem);  Fp += EW;  g_ew[pos] = EW
//   C) ACC = Fp @ Wa (smem); lrelu*va head-sum -> exp -> g_ex[pos], segsum
// ---------------------------------------------------------------------------
__global__ void __launch_bounds__(256)
pass1_kernel(
    const int* __restrict__ zn,
    const float* __restrict__ dist, const int* __restrict__ eidx,
    const float* __restrict__ wig,
    const float* __restrict__ fs_emb_s, const float* __restrict__ fs_emb_t,
    const float* __restrict__ fs_wd, const float* __restrict__ fs_We,
    const float* __restrict__ fs_Wa, const float* __restrict__ fs_va,
    const float* __restrict__ dn_emb_s, const float* __restrict__ dn_emb_t,
    const float* __restrict__ dn_wd, const float* __restrict__ dn_We,
    const float* __restrict__ dn_Wa, const float* __restrict__ dn_va)
{
    __shared__ float Fp[EPC][65];
    __shared__ float E [EPC][33];
    __shared__ float Wsm[64][64];
    __shared__ float sh_d0[8][8][MDIM];
    __shared__ int   sh_ed[EPC], sh_s[EPC], sh_dd[EPC];

    const int tid  = threadIdx.x;
    const int w    = tid >> 5;
    const int lane = tid & 31;
    const int pos0 = blockIdx.x * EPC;
    const int cnt0 = g_cnt[0];

    // CTA-wide index load (clamped for tail CTA)
    if (tid < EPC) {
        int p  = pos0 + tid; if (p > NE - 1) p = NE - 1;
        int ed = g_order[p];
        sh_ed[tid] = ed;
        sh_s [tid] = eidx[ed];
        sh_dd[tid] = eidx[NE + ed];
    }
    __syncthreads();

    const int bstart = (pos0 >= cnt0) ? 1 : 0;
    const int bend   = (pos0 + EPC - 1 >= cnt0) ? 1 : 0;

    for (int bv = bstart; bv <= bend; bv++) {
        const float* emb_s = bv ? dn_emb_s : fs_emb_s;
        const float* emb_t = bv ? dn_emb_t : fs_emb_t;
        const float* wd    = bv ? dn_wd    : fs_wd;
        const float* We    = bv ? dn_We    : fs_We;
        const float* Wa    = bv ? dn_Wa    : fs_Wa;
        const float* va    = bv ? dn_va    : fs_va;
        const float* GS0   = g_G[2 * bv];
        const float* GT0   = g_G[2 * bv + 1];

        if (bv != bstart) __syncthreads();   // protect smem reuse across iterations

        // ---- stage A: per-warp, 8 edges each ----
        // D0 rows: lane (j,q) loads float4 q of edge j
        {
            int j = lane >> 2, q = lane & 3;
            int e = w * 8 + j;
            float4 v = *(const float4*)(wig + (size_t)sh_ed[e] * 256 + q * 4);
            *(float4*)&sh_d0[w][j][q * 4] = v;
        }
        __syncwarp();

        float wdl = wd[lane];
#pragma unroll
        for (int j = 0; j < 8; j++) {
            int e = w * 8 + j;
            const float* GSb = GS0 + (size_t)sh_s[e]  * (MDIM * HDIM);
            const float* GTb = GT0 + (size_t)sh_dd[e] * (MDIM * HDIM);
            float2 f0 = make_float2(0.f, 0.f);
#pragma unroll
            for (int n = 0; n < MDIM; n++) {
                float dn = sh_d0[w][j][n];
                float2 a = *(const float2*)(GSb + n * HDIM + 2 * lane);
                float2 b = *(const float2*)(GTb + n * HDIM + 2 * lane);
                f0.x += dn * (a.x + b.x);
                f0.y += dn * (a.y + b.y);
            }
            Fp[e][2 * lane]     = f0.x;
            Fp[e][2 * lane + 1] = f0.y;

            int zs = zn[sh_s[e]], zd = zn[sh_dd[e]];
            float dd = dist[sh_ed[e]];
            E[e][lane] = silu_f(dd * wdl + emb_s[zs * CEDIM + lane] + emb_t[zd * CEDIM + lane]);
        }

        // load We into Wsm[0..31]
        {
            int base = tid * 8;
            int r = base >> 6, c = base & 63;
            *(float4*)&Wsm[r][c]     = *(const float4*)(We + r * 64 + c);
            *(float4*)&Wsm[r][c + 4] = *(const float4*)(We + r * 64 + c + 4);
        }
        __syncthreads();

        const int col = tid & 15, row = tid >> 4;
        const int e0 = row * 4, o0 = col * 4;

        // ---- stage B: EW = E @ We ----
        unsigned long long acc[4][2];
#pragma unroll
        for (int i = 0; i < 4; i++) { acc[i][0] = 0ull; acc[i][1] = 0ull; }
#pragma unroll 4
        for (int k = 0; k < CEDIM; k++) {
            unsigned long long b0 = *(const unsigned long long*)&Wsm[k][o0];
            unsigned long long b1 = *(const unsigned long long*)&Wsm[k][o0 + 2];
#pragma unroll
            for (int i = 0; i < 4; i++) {
                float a = E[e0 + i][k];
                unsigned long long aa;
                asm("mov.b64 %0, {%1, %1};" : "=l"(aa) : "f"(a));
                asm("fma.rn.f32x2 %0, %1, %2, %0;" : "+l"(acc[i][0]) : "l"(aa), "l"(b0));
                asm("fma.rn.f32x2 %0, %1, %2, %0;" : "+l"(acc[i][1]) : "l"(aa), "l"(b1));
            }
        }
#pragma unroll
        for (int i = 0; i < 4; i++) {
            float2 p0 = *(float2*)&acc[i][0];
            float2 p1 = *(float2*)&acc[i][1];
            Fp[e0 + i][o0]     += p0.x;
            Fp[e0 + i][o0 + 1] += p0.y;
            Fp[e0 + i][o0 + 2] += p1.x;
            Fp[e0 + i][o0 + 3] += p1.y;
            int pos = pos0 + e0 + i;
            int bOf = (pos >= cnt0) ? 1 : 0;
            if (pos < NE && bOf == bv) {
                float4 v = make_float4(p0.x, p0.y, p1.x, p1.y);
                *(float4*)(g_ew + (size_t)pos * HDIM + o0) = v;
            }
        }
        __syncthreads();

        // load Wa into Wsm[0..63]
        {
#pragma unroll
            for (int q = 0; q < 4; q++) {
                int idx = tid * 16 + q * 4;
                int r = idx >> 6, c = idx & 63;
                *(float4*)&Wsm[r][c] = *(const float4*)(Wa + r * 64 + c);
            }
        }
        __syncthreads();

        // ---- stage C: ACC = Fp @ Wa ----
#pragma unroll
        for (int i = 0; i < 4; i++) { acc[i][0] = 0ull; acc[i][1] = 0ull; }
#pragma unroll 4
        for (int k = 0; k < HDIM; k++) {
            unsigned long long b0 = *(const unsigned long long*)&Wsm[k][o0];
            unsigned long long b1 = *(const unsigned long long*)&Wsm[k][o0 + 2];
#pragma unroll
            for (int i = 0; i < 4; i++) {
                float a = Fp[e0 + i][k];
                unsigned long long aa;
                asm("mov.b64 %0, {%1, %1};" : "=l"(aa) : "f"(a));
                asm("fma.rn.f32x2 %0, %1, %2, %0;" : "+l"(acc[i][0]) : "l"(aa), "l"(b0));
                asm("fma.rn.f32x2 %0, %1, %2, %0;" : "+l"(acc[i][1]) : "l"(aa), "l"(b1));
            }
        }

        // epilogue: lrelu, *va, half-head sums, pair with col^1, exp + segsum
        const int head = col >> 1;
        float4 vav = *(const float4*)(va + head * 8 + (col & 1) * 4);
#pragma unroll
        for (int i = 0; i < 4; i++) {
            float2 p0 = *(float2*)&acc[i][0];
            float2 p1 = *(float2*)&acc[i][1];
            float v0 = p0.x > 0.f ? p0.x : 0.2f * p0.x;
            float v1 = p0.y > 0.f ? p0.y : 0.2f * p0.y;
            float v2 = p1.x > 0.f ? p1.x : 0.2f * p1.x;
            float v3 = p1.y > 0.f ? p1.y : 0.2f * p1.y;
            float part = v0 * vav.x + v1 * vav.y + v2 * vav.z + v3 * vav.w;
            float sum = part + __shfl_xor_sync(0xffffffffu, part, 1);
            if ((col & 1) == 0) {
                int pos = pos0 + e0 + i;
                int bOf = (pos >= cnt0) ? 1 : 0;
                if (pos < NE && bOf == bv) {
                    float ex = expf(sum);
                    g_ex[(size_t)pos * NHEADS + head] = ex;
                    atomicAdd(&g_segsum[sh_dd[e0 + i] * NHEADS + head], ex);
                }
            }
        }
    }
}

// ---------------------------------------------------------------------------
// K2: output contributions.  One warp per position.
// ---------------------------------------------------------------------------
__global__ void __launch_bounds__(256)
pass2_kernel(const int* __restrict__ eidx, const float* __restrict__ wig,
             float* __restrict__ out)
{
    __shared__ float sh_al[8][NHEADS];

    const int w    = threadIdx.x >> 5;
    const int lane = threadIdx.x & 31;
    const int pos  = blockIdx.x * 8 + w;
    if (pos >= NE) return;

    const int ed  = g_order[pos];
    const int s   = eidx[ed];
    const int d   = eidx[NE + ed];
    const int blk = (pos >= g_cnt[0]) ? 1 : 0;

    if (lane < NHEADS) {
        float ex = g_ex[(size_t)pos * NHEADS + lane];
        sh_al[w][lane] = ex / (g_segsum[d * NHEADS + lane] + 1e-9f);
    }
    __syncwarp();

    float2 q = make_float2(0.f, 0.f);
#pragma unroll
    for (int head = 0; head < NHEADS; head++) {
        float al = sh_al[w][head];
        float2 p = *(const float2*)&g_PT[blk][head * HDIM + 2 * lane];
        q.x += al * p.x; q.y += al * p.y;
    }

    const float* GSb = g_G[2 * blk]     + (size_t)s * (MDIM * HDIM);
    const float* GTb = g_G[2 * blk + 1] + (size_t)d * (MDIM * HDIM);

    float2 a1 = *(const float2*)(GSb + 1 * HDIM + 2 * lane);
    float2 b1 = *(const float2*)(GTb + 1 * HDIM + 2 * lane);
    float2 a2 = *(const float2*)(GSb + 2 * HDIM + 2 * lane);
    float2 b2 = *(const float2*)(GTb + 2 * HDIM + 2 * lane);
    float2 a3 = *(const float2*)(GSb + 3 * HDIM + 2 * lane);
    float2 b3 = *(const float2*)(GTb + 3 * HDIM + 2 * lane);
    float2 ew = *(const float2*)(g_ew + (size_t)pos * HDIM + 2 * lane);

    float p1 = q.x * (a1.x + b1.x) + q.y * (a1.y + b1.y);
    float p2 = q.x * (a2.x + b2.x) + q.y * (a2.y + b2.y);
    float p3 = q.x * (a3.x + b3.x) + q.y * (a3.y + b3.y);
    float tp = q.x * ew.x + q.y * ew.y;

#pragma unroll
    for (int off = 16; off >= 1; off >>= 1) {
        p1 += __shfl_down_sync(0xffffffffu, p1, off);
        p2 += __shfl_down_sync(0xffffffffu, p2, off);
        p3 += __shfl_down_sync(0xffffffffu, p3, off);
        tp += __shfl_down_sync(0xffffffffu, tp, off);
    }

    if (lane == 0) {
        float4 w0 = *(const float4*)(wig + (size_t)ed * 256);  // D0[0..3]
        atomicAdd(&out[d * 3 + 0], p1 + w0.y * tp);
        atomicAdd(&out[d * 3 + 1], p2 + w0.z * tp);
        atomicAdd(&out[d * 3 + 2], p3 + w0.w * tp);
    }
}

// ---------------------------------------------------------------------------
extern "C" void kernel_launch(void* const* d_in, const int* in_sizes, int n_in,
                              void* d_out, int out_size)
{
    const float* x    = (const float*)d_in[0];
    const int*   zn   = (const int*)d_in[1];
    const float* dist = (const float*)d_in[2];
    const int*   eidx = (const int*)d_in[3];
    const int*   mask = (const int*)d_in[4];
    const float* wig  = (const float*)d_in[5];

    const float* fs_emb_s = (const float*)d_in[6];
    const float* fs_emb_t = (const float*)d_in[7];
    const float* fs_wd    = (const float*)d_in[8];
    const float* fs_We    = (const float*)d_in[9];
    const float* fs_Wa    = (const float*)d_in[12];
    const float* fs_va    = (const float*)d_in[13];
    const float* fs_Ws    = (const float*)d_in[10];
    const float* fs_Wt    = (const float*)d_in[11];
    const float* fs_Wv    = (const float*)d_in[14];
    const float* fs_Wo    = (const float*)d_in[15];

    const float* dn_emb_s = (const float*)d_in[16];
    const float* dn_emb_t = (const float*)d_in[17];
    const float* dn_wd    = (const float*)d_in[18];
    const float* dn_We    = (const float*)d_in[19];
    const float* dn_Ws    = (const float*)d_in[20];
    const float* dn_Wt    = (const float*)d_in[21];
    const float* dn_Wa    = (const float*)d_in[22];
    const float* dn_va    = (const float*)d_in[23];
    const float* dn_Wv    = (const float*)d_in[24];
    const float* dn_Wo    = (const float*)d_in[25];

    float* out = (float*)d_out;

    setup_kernel<<<32, 256>>>(fs_Wv, fs_Wo, dn_Wv, dn_Wo, out);

    bucket_kernel<<<(NE + 255) / 256, 256>>>(eidx, mask);

    mm_kernel<<<dim3(NROWS / 64, 4), 128>>>(x, fs_Ws, fs_Wt, dn_Ws, dn_Wt);

    // 60000 positions / 64 per CTA = 938 CTAs (last partially filled)
    pass1_kernel<<<(NE + EPC - 1) / EPC, 256>>>(zn, dist, eidx, wig,
                                fs_emb_s, fs_emb_t, fs_wd, fs_We, fs_Wa, fs_va,
                                dn_emb_s, dn_emb_t, dn_wd, dn_We, dn_Wa, dn_va);

    pass2_kernel<<<7500, 256>>>(eidx, wig, out);
}

// round 14
// speedup vs baseline: 2.2232x; 1.0126x over previous
#include <cuda_runtime.h>
#include <math.h>

#define NN 4000
#define NE 60000
#define MDIM 16
#define CDIM 64
#define HDIM 64
#define NHEADS 8
#define ADIM 8
#define VCDIM 8
#define CEDIM 32
#define NROWS (NN * MDIM)
#define EPC 64

// ---- scratch ----
__device__ float g_G[4][(size_t)NROWS * HDIM]; // 0:fs_Ws 1:fs_Wt 2:dn_Ws 3:dn_Wt
__device__ float g_f0[(size_t)NE * HDIM];      // rotation partial per bucketed position
__device__ float g_E [(size_t)NE * CEDIM];     // silu edge embedding per bucketed position
__device__ float g_ew[(size_t)NE * HDIM];      // (e @ We) per bucketed position
__device__ float g_ex[NE * NHEADS];            // exp(logits) per bucketed position
__device__ float g_segsum[NN * NHEADS];
__device__ int   g_cnt[2];
__device__ int   g_order[NE];
__device__ float g_PT[2][NHEADS * HDIM];

__device__ __forceinline__ float silu_f(float v) { return v / (1.0f + __expf(-v)); }

// ---------------------------------------------------------------------------
// K0: zero accumulators + build PT
// ---------------------------------------------------------------------------
__global__ void setup_kernel(
    const float* __restrict__ fs_Wv, const float* __restrict__ fs_Wo,
    const float* __restrict__ dn_Wv, const float* __restrict__ dn_Wo,
    float* __restrict__ out)
{
    int tid = blockIdx.x * blockDim.x + threadIdx.x;
    int nt  = gridDim.x * blockDim.x;

    if (tid < 2) g_cnt[tid] = 0;
    for (int i = tid; i < NN * 3; i += nt) out[i] = 0.0f;
    for (int i = tid; i < NN * NHEADS; i += nt) g_segsum[i] = 0.0f;

    for (int i = tid; i < 2 * NHEADS * HDIM; i += nt) {
        int blk = i >> 9; int r = i & 511;
        int h = r >> 6; int c = r & 63;
        const float* Wv = blk ? dn_Wv : fs_Wv;
        const float* Wo = blk ? dn_Wo : fs_Wo;
        float acc = 0.0f;
#pragma unroll
        for (int vc = 0; vc < VCDIM; vc++)
            acc += Wv[c * (NHEADS * VCDIM) + h * VCDIM + vc] * Wo[h * VCDIM + vc];
        g_PT[blk][h * HDIM + c] = acc;
    }
}

// ---------------------------------------------------------------------------
// K0b: bucket edges by blk = mask[dst]
// ---------------------------------------------------------------------------
__global__ void bucket_kernel(const int* __restrict__ eidx, const int* __restrict__ mask)
{
    int e = blockIdx.x * blockDim.x + threadIdx.x;
    bool valid = e < NE;
    int b = 0;
    if (valid) b = (mask[eidx[NE + e]] != 0) ? 1 : 0;
    unsigned m1 = __ballot_sync(0xffffffffu, valid && (b == 1));
    unsigned m0 = __ballot_sync(0xffffffffu, valid && (b == 0));
    int lane = threadIdx.x & 31;
    int base0 = 0, base1 = 0;
    if (lane == 0) {
        int n0 = __popc(m0), n1 = __popc(m1);
        if (n0) base0 = atomicAdd(&g_cnt[0], n0);
        if (n1) base1 = atomicAdd(&g_cnt[1], n1);
    }
    base0 = __shfl_sync(0xffffffffu, base0, 0);
    base1 = __shfl_sync(0xffffffffu, base1, 0);
    unsigned lt = (1u << lane) - 1u;
    if (valid) {
        int pos;
        if (b) pos = NE - 1 - (base1 + __popc(m1 & lt));
        else   pos = base0 + __popc(m0 & lt);
        g_order[pos] = e;
    }
}

// ---------------------------------------------------------------------------
// K0c: G tables.  C[64000,64] = X[64000,64] @ W[64,64] for 4 weight matrices.
// ---------------------------------------------------------------------------
__global__ void __launch_bounds__(128)
mm_kernel(const float* __restrict__ x,
          const float* __restrict__ fs_Ws, const float* __restrict__ fs_Wt,
          const float* __restrict__ dn_Ws, const float* __restrict__ dn_Wt)
{
    __shared__ float Xs[64][65];
    __shared__ float Wsm[64][64];

    const int m = blockIdx.y;
    const float* W = (m == 0) ? fs_Ws : (m == 1) ? fs_Wt : (m == 2) ? dn_Ws : dn_Wt;
    const int row0 = blockIdx.x * 64;
    const int tid  = threadIdx.x;

#pragma unroll
    for (int i = 0; i < 8; i++) {
        int f4 = i * 128 + tid;
        int r = f4 >> 4, c4 = (f4 & 15) * 4;
        float4 v = *(const float4*)(x + (size_t)(row0 + r) * 64 + c4);
        Xs[r][c4] = v.x; Xs[r][c4 + 1] = v.y; Xs[r][c4 + 2] = v.z; Xs[r][c4 + 3] = v.w;
        *(float4*)&Wsm[r][c4] = *(const float4*)(W + r * 64 + c4);
    }
    __syncthreads();

    const int tc = tid & 15, tr = tid >> 4;
    const int c0 = tc * 4, r0 = tr * 8;

    unsigned long long acc[8][2];
#pragma unroll
    for (int i = 0; i < 8; i++) { acc[i][0] = 0ull; acc[i][1] = 0ull; }

#pragma unroll 4
    for (int k = 0; k < 64; k++) {
        unsigned long long b0 = *(const unsigned long long*)&Wsm[k][c0];
        unsigned long long b1 = *(const unsigned long long*)&Wsm[k][c0 + 2];
#pragma unroll
        for (int i = 0; i < 8; i++) {
            float a = Xs[r0 + i][k];
            unsigned long long aa;
            asm("mov.b64 %0, {%1, %1};" : "=l"(aa) : "f"(a));
            asm("fma.rn.f32x2 %0, %1, %2, %0;" : "+l"(acc[i][0]) : "l"(aa), "l"(b0));
            asm("fma.rn.f32x2 %0, %1, %2, %0;" : "+l"(acc[i][1]) : "l"(aa), "l"(b1));
        }
    }

    float* outp = g_G[m];
#pragma unroll
    for (int i = 0; i < 8; i++) {
        float2 p0 = *(float2*)&acc[i][0];
        float2 p1 = *(float2*)&acc[i][1];
        float4 v = make_float4(p0.x, p0.y, p1.x, p1.y);
        *(float4*)(outp + (size_t)(row0 + r0 + i) * 64 + c0) = v;
    }
}

// ---------------------------------------------------------------------------
// K1a: gather kernel.  One warp per bucketed position; no smem.
// ---------------------------------------------------------------------------
__global__ void __launch_bounds__(256)
gather_kernel(
    const int* __restrict__ zn,
    const float* __restrict__ dist, const int* __restrict__ eidx,
    const float* __restrict__ wig,
    const float* __restrict__ fs_emb_s, const float* __restrict__ fs_emb_t,
    const float* __restrict__ fs_wd,
    const float* __restrict__ dn_emb_s, const float* __restrict__ dn_emb_t,
    const float* __restrict__ dn_wd)
{
    const int w    = threadIdx.x >> 5;
    const int lane = threadIdx.x & 31;
    const int pos  = blockIdx.x * 8 + w;
    if (pos >= NE) return;

    const int ed  = g_order[pos];
    const int s   = eidx[ed];
    const int d   = eidx[NE + ed];
    const int blk = (pos >= g_cnt[0]) ? 1 : 0;

    float vd0 = (lane < MDIM) ? wig[(size_t)ed * 256 + lane] : 0.f;

    const float* GSb = g_G[2 * blk]     + (size_t)s * (MDIM * HDIM);
    const float* GTb = g_G[2 * blk + 1] + (size_t)d * (MDIM * HDIM);

    float2 f0 = make_float2(0.f, 0.f);
#pragma unroll
    for (int n = 0; n < MDIM; n++) {
        float dn = __shfl_sync(0xffffffffu, vd0, n);
        float2 a = *(const float2*)(GSb + n * HDIM + 2 * lane);
        float2 b = *(const float2*)(GTb + n * HDIM + 2 * lane);
        f0.x += dn * (a.x + b.x);
        f0.y += dn * (a.y + b.y);
    }
    *(float2*)(g_f0 + (size_t)pos * HDIM + 2 * lane) = f0;

    const float* emb_s = blk ? dn_emb_s : fs_emb_s;
    const float* emb_t = blk ? dn_emb_t : fs_emb_t;
    const float* wd    = blk ? dn_wd    : fs_wd;
    int zs = zn[s], zd = zn[d];
    float dd = dist[ed];
    g_E[(size_t)pos * CEDIM + lane] =
        silu_f(dd * wd[lane] + emb_s[zs * CEDIM + lane] + emb_t[zd * CEDIM + lane]);
}

// ---------------------------------------------------------------------------
// K1b: edge GEMM.  One CTA per 64 bucketed positions.
// Padding of 4 (stride 68 / 36): keeps float4 smem ops 16B-aligned AND breaks
// the row-alignment bank pattern (stride mod 32 = 4).
// ---------------------------------------------------------------------------
__global__ void __launch_bounds__(256)
edge_gemm_kernel(
    const int* __restrict__ eidx,
    const float* __restrict__ fs_We, const float* __restrict__ fs_Wa, const float* __restrict__ fs_va,
    const float* __restrict__ dn_We, const float* __restrict__ dn_Wa, const float* __restrict__ dn_va)
{
    __shared__ __align__(16) float Fp[EPC][68];
    __shared__ __align__(16) float E [EPC][36];
    __shared__ __align__(16) float Wsm[64][64];
    __shared__ int   sh_dd[EPC];

    const int tid  = threadIdx.x;
    const int pos0 = blockIdx.x * EPC;
    const int cnt0 = g_cnt[0];

    if (tid < EPC) {
        int p  = pos0 + tid; if (p > NE - 1) p = NE - 1;
        sh_dd[tid] = eidx[NE + g_order[p]];
    }

    const int bstart = (pos0 >= cnt0) ? 1 : 0;
    const int bend   = (pos0 + EPC - 1 >= cnt0) ? 1 : 0;

    for (int bv = bstart; bv <= bend; bv++) {
        const float* We = bv ? dn_We : fs_We;
        const float* Wa = bv ? dn_Wa : fs_Wa;
        const float* va = bv ? dn_va : fs_va;

        if (bv != bstart) __syncthreads();

        // load Fp tile (64x64), E tile (64x32), We
        {
            const float* src = g_f0 + (size_t)pos0 * HDIM;
#pragma unroll
            for (int q = 0; q < 4; q++) {
                int i = tid * 16 + q * 4;
                int e = i >> 6, c = i & 63;
                *(float4*)&Fp[e][c] = *(const float4*)(src + i);
            }
            const float* esrc = g_E + (size_t)pos0 * CEDIM;
#pragma unroll
            for (int q = 0; q < 2; q++) {
                int i = tid * 8 + q * 4;
                int e = i >> 5, k = i & 31;
                *(float4*)&E[e][k] = *(const float4*)(esrc + i);
            }
            int base = tid * 8;
            int r = base >> 6, c = base & 63;
            *(float4*)&Wsm[r][c]     = *(const float4*)(We + r * 64 + c);
            *(float4*)&Wsm[r][c + 4] = *(const float4*)(We + r * 64 + c + 4);
        }
        __syncthreads();

        const int col = tid & 15, row = tid >> 4;
        const int e0 = row * 4, o0 = col * 4;

        // ---- EW = E @ We ----
        unsigned long long acc[4][2];
#pragma unroll
        for (int i = 0; i < 4; i++) { acc[i][0] = 0ull; acc[i][1] = 0ull; }
#pragma unroll 4
        for (int k = 0; k < CEDIM; k++) {
            unsigned long long b0 = *(const unsigned long long*)&Wsm[k][o0];
            unsigned long long b1 = *(const unsigned long long*)&Wsm[k][o0 + 2];
#pragma unroll
            for (int i = 0; i < 4; i++) {
                float a = E[e0 + i][k];
                unsigned long long aa;
                asm("mov.b64 %0, {%1, %1};" : "=l"(aa) : "f"(a));
                asm("fma.rn.f32x2 %0, %1, %2, %0;" : "+l"(acc[i][0]) : "l"(aa), "l"(b0));
                asm("fma.rn.f32x2 %0, %1, %2, %0;" : "+l"(acc[i][1]) : "l"(aa), "l"(b1));
            }
        }
#pragma unroll
        for (int i = 0; i < 4; i++) {
            float2 p0 = *(float2*)&acc[i][0];
            float2 p1 = *(float2*)&acc[i][1];
            Fp[e0 + i][o0]     += p0.x;
            Fp[e0 + i][o0 + 1] += p0.y;
            Fp[e0 + i][o0 + 2] += p1.x;
            Fp[e0 + i][o0 + 3] += p1.y;
            int pos = pos0 + e0 + i;
            int bOf = (pos >= cnt0) ? 1 : 0;
            if (pos < NE && bOf == bv) {
                float4 v = make_float4(p0.x, p0.y, p1.x, p1.y);
                *(float4*)(g_ew + (size_t)pos * HDIM + o0) = v;
            }
        }
        __syncthreads();

        // load Wa
        {
#pragma unroll
            for (int q = 0; q < 4; q++) {
                int idx = tid * 16 + q * 4;
                int r = idx >> 6, c = idx & 63;
                *(float4*)&Wsm[r][c] = *(const float4*)(Wa + r * 64 + c);
            }
        }
        __syncthreads();

        // ---- ACC = Fp @ Wa ----
#pragma unroll
        for (int i = 0; i < 4; i++) { acc[i][0] = 0ull; acc[i][1] = 0ull; }
#pragma unroll 4
        for (int k = 0; k < HDIM; k++) {
            unsigned long long b0 = *(const unsigned long long*)&Wsm[k][o0];
            unsigned long long b1 = *(const unsigned long long*)&Wsm[k][o0 + 2];
#pragma unroll
            for (int i = 0; i < 4; i++) {
                float a = Fp[e0 + i][k];
                unsigned long long aa;
                asm("mov.b64 %0, {%1, %1};" : "=l"(aa) : "f"(a));
                asm("fma.rn.f32x2 %0, %1, %2, %0;" : "+l"(acc[i][0]) : "l"(aa), "l"(b0));
                asm("fma.rn.f32x2 %0, %1, %2, %0;" : "+l"(acc[i][1]) : "l"(aa), "l"(b1));
            }
        }

        // epilogue
        const int head = col >> 1;
        float4 vav = *(const float4*)(va + head * 8 + (col & 1) * 4);
#pragma unroll
        for (int i = 0; i < 4; i++) {
            float2 p0 = *(float2*)&acc[i][0];
            float2 p1 = *(float2*)&acc[i][1];
            float v0 = p0.x > 0.f ? p0.x : 0.2f * p0.x;
            float v1 = p0.y > 0.f ? p0.y : 0.2f * p0.y;
            float v2 = p1.x > 0.f ? p1.x : 0.2f * p1.x;
            float v3 = p1.y > 0.f ? p1.y : 0.2f * p1.y;
            float part = v0 * vav.x + v1 * vav.y + v2 * vav.z + v3 * vav.w;
            float sum = part + __shfl_xor_sync(0xffffffffu, part, 1);
            if ((col & 1) == 0) {
                int pos = pos0 + e0 + i;
                int bOf = (pos >= cnt0) ? 1 : 0;
                if (pos < NE && bOf == bv) {
                    float ex = expf(sum);
                    g_ex[(size_t)pos * NHEADS + head] = ex;
                    atomicAdd(&g_segsum[sh_dd[e0 + i] * NHEADS + head], ex);
                }
            }
        }
    }
}

// ---------------------------------------------------------------------------
// K2: output contributions.  One warp per position.
// ---------------------------------------------------------------------------
__global__ void __launch_bounds__(256)
pass2_kernel(const int* __restrict__ eidx, const float* __restrict__ wig,
             float* __restrict__ out)
{
    __shared__ float sh_al[8][NHEADS];

    const int w    = threadIdx.x >> 5;
    const int lane = threadIdx.x & 31;
    const int pos  = blockIdx.x * 8 + w;
    if (pos >= NE) return;

    const int ed  = g_order[pos];
    const int s   = eidx[ed];
    const int d   = eidx[NE + ed];
    const int blk = (pos >= g_cnt[0]) ? 1 : 0;

    if (lane < NHEADS) {
        float ex = g_ex[(size_t)pos * NHEADS + lane];
        sh_al[w][lane] = ex / (g_segsum[d * NHEADS + lane] + 1e-9f);
    }
    __syncwarp();

    float2 q = make_float2(0.f, 0.f);
#pragma unroll
    for (int head = 0; head < NHEADS; head++) {
        float al = sh_al[w][head];
        float2 p = *(const float2*)&g_PT[blk][head * HDIM + 2 * lane];
        q.x += al * p.x; q.y += al * p.y;
    }

    const float* GSb = g_G[2 * blk]     + (size_t)s * (MDIM * HDIM);
    const float* GTb = g_G[2 * blk + 1] + (size_t)d * (MDIM * HDIM);

    float2 a1 = *(const float2*)(GSb + 1 * HDIM + 2 * lane);
    float2 b1 = *(const float2*)(GTb + 1 * HDIM + 2 * lane);
    float2 a2 = *(const float2*)(GSb + 2 * HDIM + 2 * lane);
    float2 b2 = *(const float2*)(GTb + 2 * HDIM + 2 * lane);
    float2 a3 = *(const float2*)(GSb + 3 * HDIM + 2 * lane);
    float2 b3 = *(const float2*)(GTb + 3 * HDIM + 2 * lane);
    float2 ew = *(const float2*)(g_ew + (size_t)pos * HDIM + 2 * lane);

    float p1 = q.x * (a1.x + b1.x) + q.y * (a1.y + b1.y);
    float p2 = q.x * (a2.x + b2.x) + q.y * (a2.y + b2.y);
    float p3 = q.x * (a3.x + b3.x) + q.y * (a3.y + b3.y);
    float tp = q.x * ew.x + q.y * ew.y;

#pragma unroll
    for (int off = 16; off >= 1; off >>= 1) {
        p1 += __shfl_down_sync(0xffffffffu, p1, off);
        p2 += __shfl_down_sync(0xffffffffu, p2, off);
        p3 += __shfl_down_sync(0xffffffffu, p3, off);
        tp += __shfl_down_sync(0xffffffffu, tp, off);
    }

    if (lane == 0) {
        float4 w0 = *(const float4*)(wig + (size_t)ed * 256);
        atomicAdd(&out[d * 3 + 0], p1 + w0.y * tp);
        atomicAdd(&out[d * 3 + 1], p2 + w0.z * tp);
        atomicAdd(&out[d * 3 + 2], p3 + w0.w * tp);
    }
}

// ---------------------------------------------------------------------------
extern "C" void kernel_launch(void* const* d_in, const int* in_sizes, int n_in,
                              void* d_out, int out_size)
{
    const float* x    = (const float*)d_in[0];
    const int*   zn   = (const int*)d_in[1];
    const float* dist = (const float*)d_in[2];
    const int*   eidx = (const int*)d_in[3];
    const int*   mask = (const int*)d_in[4];
    const float* wig  = (const float*)d_in[5];

    const float* fs_emb_s = (const float*)d_in[6];
    const float* fs_emb_t = (const float*)d_in[7];
    const float* fs_wd    = (const float*)d_in[8];
    const float* fs_We    = (const float*)d_in[9];
    const float* fs_Ws    = (const float*)d_in[10];
    const float* fs_Wt    = (const float*)d_in[11];
    const float* fs_Wa    = (const float*)d_in[12];
    const float* fs_va    = (const float*)d_in[13];
    const float* fs_Wv    = (const float*)d_in[14];
    const float* fs_Wo    = (const float*)d_in[15];

    const float* dn_emb_s = (const float*)d_in[16];
    const float* dn_emb_t = (const float*)d_in[17];
    const float* dn_wd    = (const float*)d_in[18];
    const float* dn_We    = (const float*)d_in[19];
    const float* dn_Ws    = (const float*)d_in[20];
    const float* dn_Wt    = (const float*)d_in[21];
    const float* dn_Wa    = (const float*)d_in[22];
    const float* dn_va    = (const float*)d_in[23];
    const float* dn_Wv    = (const float*)d_in[24];
    const float* dn_Wo    = (const float*)d_in[25];

    float* out = (float*)d_out;

    setup_kernel<<<32, 256>>>(fs_Wv, fs_Wo, dn_Wv, dn_Wo, out);

    bucket_kernel<<<(NE + 255) / 256, 256>>>(eidx, mask);

    mm_kernel<<<dim3(NROWS / 64, 4), 128>>>(x, fs_Ws, fs_Wt, dn_Ws, dn_Wt);

    gather_kernel<<<7500, 256>>>(zn, dist, eidx, wig,
                                 fs_emb_s, fs_emb_t, fs_wd,
                                 dn_emb_s, dn_emb_t, dn_wd);

    edge_gemm_kernel<<<(NE + EPC - 1) / EPC, 256>>>(eidx,
                                 fs_We, fs_Wa, fs_va,
                                 dn_We, dn_Wa, dn_va);

    pass2_kernel<<<7500, 256>>>(eidx, wig, out);
}

// round 15
// speedup vs baseline: 2.4457x; 1.1001x over previous
#include <cuda_runtime.h>
#include <cuda_fp16.h>
#include <math.h>

#define NN 4000
#define NE 60000
#define MDIM 16
#define CDIM 64
#define HDIM 64
#define NHEADS 8
#define ADIM 8
#define VCDIM 8
#define CEDIM 32
#define NROWS (NN * MDIM)
#define EPC 64
#define H2   (HDIM / 2)                 // 32 half2 per row

// ---- scratch ----
__device__ __half2 g_G2[4][(size_t)NROWS * H2]; // fp16 G tables: 0:fs_Ws 1:fs_Wt 2:dn_Ws 3:dn_Wt
__device__ float g_f0[(size_t)NE * HDIM];       // rotation partial per bucketed position
__device__ float g_E [(size_t)NE * CEDIM];      // silu edge embedding per bucketed position
__device__ float g_ew[(size_t)NE * HDIM];       // (e @ We) per bucketed position
__device__ float g_ex[NE * NHEADS];             // exp(logits) per bucketed position
__device__ float g_segsum[NN * NHEADS];
__device__ int   g_cnt[2];
__device__ int   g_order[NE];
__device__ float g_PT[2][NHEADS * HDIM];

__device__ __forceinline__ float silu_f(float v) { return v / (1.0f + __expf(-v)); }

// ---------------------------------------------------------------------------
// K0: zero accumulators + build PT
// ---------------------------------------------------------------------------
__global__ void setup_kernel(
    const float* __restrict__ fs_Wv, const float* __restrict__ fs_Wo,
    const float* __restrict__ dn_Wv, const float* __restrict__ dn_Wo,
    float* __restrict__ out)
{
    int tid = blockIdx.x * blockDim.x + threadIdx.x;
    int nt  = gridDim.x * blockDim.x;

    if (tid < 2) g_cnt[tid] = 0;
    for (int i = tid; i < NN * 3; i += nt) out[i] = 0.0f;
    for (int i = tid; i < NN * NHEADS; i += nt) g_segsum[i] = 0.0f;

    for (int i = tid; i < 2 * NHEADS * HDIM; i += nt) {
        int blk = i >> 9; int r = i & 511;
        int h = r >> 6; int c = r & 63;
        const float* Wv = blk ? dn_Wv : fs_Wv;
        const float* Wo = blk ? dn_Wo : fs_Wo;
        float acc = 0.0f;
#pragma unroll
        for (int vc = 0; vc < VCDIM; vc++)
            acc += Wv[c * (NHEADS * VCDIM) + h * VCDIM + vc] * Wo[h * VCDIM + vc];
        g_PT[blk][h * HDIM + c] = acc;
    }
}

// ---------------------------------------------------------------------------
// K0b: bucket edges by blk = mask[dst]
// ---------------------------------------------------------------------------
__global__ void bucket_kernel(const int* __restrict__ eidx, const int* __restrict__ mask)
{
    int e = blockIdx.x * blockDim.x + threadIdx.x;
    bool valid = e < NE;
    int b = 0;
    if (valid) b = (mask[eidx[NE + e]] != 0) ? 1 : 0;
    unsigned m1 = __ballot_sync(0xffffffffu, valid && (b == 1));
    unsigned m0 = __ballot_sync(0xffffffffu, valid && (b == 0));
    int lane = threadIdx.x & 31;
    int base0 = 0, base1 = 0;
    if (lane == 0) {
        int n0 = __popc(m0), n1 = __popc(m1);
        if (n0) base0 = atomicAdd(&g_cnt[0], n0);
        if (n1) base1 = atomicAdd(&g_cnt[1], n1);
    }
    base0 = __shfl_sync(0xffffffffu, base0, 0);
    base1 = __shfl_sync(0xffffffffu, base1, 0);
    unsigned lt = (1u << lane) - 1u;
    if (valid) {
        int pos;
        if (b) pos = NE - 1 - (base1 + __popc(m1 & lt));
        else   pos = base0 + __popc(m0 & lt);
        g_order[pos] = e;
    }
}

// ---------------------------------------------------------------------------
// K0c: G tables (fp16).  C[64000,64] = X[64000,64] @ W[64,64], 4 matrices.
// ---------------------------------------------------------------------------
__global__ void __launch_bounds__(128)
mm_kernel(const float* __restrict__ x,
          const float* __restrict__ fs_Ws, const float* __restrict__ fs_Wt,
          const float* __restrict__ dn_Ws, const float* __restrict__ dn_Wt)
{
    __shared__ float Xs[64][65];
    __shared__ float Wsm[64][64];

    const int m = blockIdx.y;
    const float* W = (m == 0) ? fs_Ws : (m == 1) ? fs_Wt : (m == 2) ? dn_Ws : dn_Wt;
    const int row0 = blockIdx.x * 64;
    const int tid  = threadIdx.x;

#pragma unroll
    for (int i = 0; i < 8; i++) {
        int f4 = i * 128 + tid;
        int r = f4 >> 4, c4 = (f4 & 15) * 4;
        float4 v = *(const float4*)(x + (size_t)(row0 + r) * 64 + c4);
        Xs[r][c4] = v.x; Xs[r][c4 + 1] = v.y; Xs[r][c4 + 2] = v.z; Xs[r][c4 + 3] = v.w;
        *(float4*)&Wsm[r][c4] = *(const float4*)(W + r * 64 + c4);
    }
    __syncthreads();

    const int tc = tid & 15, tr = tid >> 4;
    const int c0 = tc * 4, r0 = tr * 8;

    unsigned long long acc[8][2];
#pragma unroll
    for (int i = 0; i < 8; i++) { acc[i][0] = 0ull; acc[i][1] = 0ull; }

#pragma unroll 4
    for (int k = 0; k < 64; k++) {
        unsigned long long b0 = *(const unsigned long long*)&Wsm[k][c0];
        unsigned long long b1 = *(const unsigned long long*)&Wsm[k][c0 + 2];
#pragma unroll
        for (int i = 0; i < 8; i++) {
            float a = Xs[r0 + i][k];
            unsigned long long aa;
            asm("mov.b64 %0, {%1, %1};" : "=l"(aa) : "f"(a));
            asm("fma.rn.f32x2 %0, %1, %2, %0;" : "+l"(acc[i][0]) : "l"(aa), "l"(b0));
            asm("fma.rn.f32x2 %0, %1, %2, %0;" : "+l"(acc[i][1]) : "l"(aa), "l"(b1));
        }
    }

    __half2* outp = g_G2[m];
#pragma unroll
    for (int i = 0; i < 8; i++) {
        float2 p0 = *(float2*)&acc[i][0];
        float2 p1 = *(float2*)&acc[i][1];
        __half2 h0 = __floats2half2_rn(p0.x, p0.y);
        __half2 h1 = __floats2half2_rn(p1.x, p1.y);
        // c0 multiple of 4 -> half2 index c0/2 even -> 8B-aligned store
        __half2* dst = outp + (size_t)(row0 + r0 + i) * H2 + (c0 >> 1);
        *(uint*)&dst[0] = *(uint*)&h0;
        *(uint*)&dst[1] = *(uint*)&h1;
    }
}

// ---------------------------------------------------------------------------
// K1a: gather kernel.  One warp per bucketed position; no smem.
// G reads now fp16: one half2 per lane per row.
// ---------------------------------------------------------------------------
__global__ void __launch_bounds__(256)
gather_kernel(
    const int* __restrict__ zn,
    const float* __restrict__ dist, const int* __restrict__ eidx,
    const float* __restrict__ wig,
    const float* __restrict__ fs_emb_s, const float* __restrict__ fs_emb_t,
    const float* __restrict__ fs_wd,
    const float* __restrict__ dn_emb_s, const float* __restrict__ dn_emb_t,
    const float* __restrict__ dn_wd)
{
    const int w    = threadIdx.x >> 5;
    const int lane = threadIdx.x & 31;
    const int pos  = blockIdx.x * 8 + w;
    if (pos >= NE) return;

    const int ed  = g_order[pos];
    const int s   = eidx[ed];
    const int d   = eidx[NE + ed];
    const int blk = (pos >= g_cnt[0]) ? 1 : 0;

    float vd0 = (lane < MDIM) ? wig[(size_t)ed * 256 + lane] : 0.f;

    const __half2* GSb = g_G2[2 * blk]     + (size_t)s * (MDIM * H2);
    const __half2* GTb = g_G2[2 * blk + 1] + (size_t)d * (MDIM * H2);

    float2 f0 = make_float2(0.f, 0.f);
#pragma unroll
    for (int n = 0; n < MDIM; n++) {
        float dn = __shfl_sync(0xffffffffu, vd0, n);
        float2 a = __half22float2(GSb[n * H2 + lane]);
        float2 b = __half22float2(GTb[n * H2 + lane]);
        f0.x += dn * (a.x + b.x);
        f0.y += dn * (a.y + b.y);
    }
    *(float2*)(g_f0 + (size_t)pos * HDIM + 2 * lane) = f0;

    const float* emb_s = blk ? dn_emb_s : fs_emb_s;
    const float* emb_t = blk ? dn_emb_t : fs_emb_t;
    const float* wd    = blk ? dn_wd    : fs_wd;
    int zs = zn[s], zd = zn[d];
    float dd = dist[ed];
    g_E[(size_t)pos * CEDIM + lane] =
        silu_f(dd * wd[lane] + emb_s[zs * CEDIM + lane] + emb_t[zd * CEDIM + lane]);
}

// ---------------------------------------------------------------------------
// K1b: edge GEMM.  One CTA per 64 bucketed positions.  (unchanged from R13)
// ---------------------------------------------------------------------------
__global__ void __launch_bounds__(256)
edge_gemm_kernel(
    const int* __restrict__ eidx,
    const float* __restrict__ fs_We, const float* __restrict__ fs_Wa, const float* __restrict__ fs_va,
    const float* __restrict__ dn_We, const float* __restrict__ dn_Wa, const float* __restrict__ dn_va)
{
    __shared__ __align__(16) float Fp[EPC][68];
    __shared__ __align__(16) float E [EPC][36];
    __shared__ __align__(16) float Wsm[64][64];
    __shared__ int   sh_dd[EPC];

    const int tid  = threadIdx.x;
    const int pos0 = blockIdx.x * EPC;
    const int cnt0 = g_cnt[0];

    if (tid < EPC) {
        int p  = pos0 + tid; if (p > NE - 1) p = NE - 1;
        sh_dd[tid] = eidx[NE + g_order[p]];
    }

    const int bstart = (pos0 >= cnt0) ? 1 : 0;
    const int bend   = (pos0 + EPC - 1 >= cnt0) ? 1 : 0;

    for (int bv = bstart; bv <= bend; bv++) {
        const float* We = bv ? dn_We : fs_We;
        const float* Wa = bv ? dn_Wa : fs_Wa;
        const float* va = bv ? dn_va : fs_va;

        if (bv != bstart) __syncthreads();

        {
            const float* src = g_f0 + (size_t)pos0 * HDIM;
#pragma unroll
            for (int q = 0; q < 4; q++) {
                int i = tid * 16 + q * 4;
                int e = i >> 6, c = i & 63;
                *(float4*)&Fp[e][c] = *(const float4*)(src + i);
            }
            const float* esrc = g_E + (size_t)pos0 * CEDIM;
#pragma unroll
            for (int q = 0; q < 2; q++) {
                int i = tid * 8 + q * 4;
                int e = i >> 5, k = i & 31;
                *(float4*)&E[e][k] = *(const float4*)(esrc + i);
            }
            int base = tid * 8;
            int r = base >> 6, c = base & 63;
            *(float4*)&Wsm[r][c]     = *(const float4*)(We + r * 64 + c);
            *(float4*)&Wsm[r][c + 4] = *(const float4*)(We + r * 64 + c + 4);
        }
        __syncthreads();

        const int col = tid & 15, row = tid >> 4;
        const int e0 = row * 4, o0 = col * 4;

        unsigned long long acc[4][2];
#pragma unroll
        for (int i = 0; i < 4; i++) { acc[i][0] = 0ull; acc[i][1] = 0ull; }
#pragma unroll 4
        for (int k = 0; k < CEDIM; k++) {
            unsigned long long b0 = *(const unsigned long long*)&Wsm[k][o0];
            unsigned long long b1 = *(const unsigned long long*)&Wsm[k][o0 + 2];
#pragma unroll
            for (int i = 0; i < 4; i++) {
                float a = E[e0 + i][k];
                unsigned long long aa;
                asm("mov.b64 %0, {%1, %1};" : "=l"(aa) : "f"(a));
                asm("fma.rn.f32x2 %0, %1, %2, %0;" : "+l"(acc[i][0]) : "l"(aa), "l"(b0));
                asm("fma.rn.f32x2 %0, %1, %2, %0;" : "+l"(acc[i][1]) : "l"(aa), "l"(b1));
            }
        }
#pragma unroll
        for (int i = 0; i < 4; i++) {
            float2 p0 = *(float2*)&acc[i][0];
            float2 p1 = *(float2*)&acc[i][1];
            Fp[e0 + i][o0]     += p0.x;
            Fp[e0 + i][o0 + 1] += p0.y;
            Fp[e0 + i][o0 + 2] += p1.x;
            Fp[e0 + i][o0 + 3] += p1.y;
            int pos = pos0 + e0 + i;
            int bOf = (pos >= cnt0) ? 1 : 0;
            if (pos < NE && bOf == bv) {
                float4 v = make_float4(p0.x, p0.y, p1.x, p1.y);
                *(float4*)(g_ew + (size_t)pos * HDIM + o0) = v;
            }
        }
        __syncthreads();

        {
#pragma unroll
            for (int q = 0; q < 4; q++) {
                int idx = tid * 16 + q * 4;
                int r = idx >> 6, c = idx & 63;
                *(float4*)&Wsm[r][c] = *(const float4*)(Wa + r * 64 + c);
            }
        }
        __syncthreads();

#pragma unroll
        for (int i = 0; i < 4; i++) { acc[i][0] = 0ull; acc[i][1] = 0ull; }
#pragma unroll 4
        for (int k = 0; k < HDIM; k++) {
            unsigned long long b0 = *(const unsigned long long*)&Wsm[k][o0];
            unsigned long long b1 = *(const unsigned long long*)&Wsm[k][o0 + 2];
#pragma unroll
            for (int i = 0; i < 4; i++) {
                float a = Fp[e0 + i][k];
                unsigned long long aa;
                asm("mov.b64 %0, {%1, %1};" : "=l"(aa) : "f"(a));
                asm("fma.rn.f32x2 %0, %1, %2, %0;" : "+l"(acc[i][0]) : "l"(aa), "l"(b0));
                asm("fma.rn.f32x2 %0, %1, %2, %0;" : "+l"(acc[i][1]) : "l"(aa), "l"(b1));
            }
        }

        const int head = col >> 1;
        float4 vav = *(const float4*)(va + head * 8 + (col & 1) * 4);
#pragma unroll
        for (int i = 0; i < 4; i++) {
            float2 p0 = *(float2*)&acc[i][0];
            float2 p1 = *(float2*)&acc[i][1];
            float v0 = p0.x > 0.f ? p0.x : 0.2f * p0.x;
            float v1 = p0.y > 0.f ? p0.y : 0.2f * p0.y;
            float v2 = p1.x > 0.f ? p1.x : 0.2f * p1.x;
            float v3 = p1.y > 0.f ? p1.y : 0.2f * p1.y;
            float part = v0 * vav.x + v1 * vav.y + v2 * vav.z + v3 * vav.w;
            float sum = part + __shfl_xor_sync(0xffffffffu, part, 1);
            if ((col & 1) == 0) {
                int pos = pos0 + e0 + i;
                int bOf = (pos >= cnt0) ? 1 : 0;
                if (pos < NE && bOf == bv) {
                    float ex = expf(sum);
                    g_ex[(size_t)pos * NHEADS + head] = ex;
                    atomicAdd(&g_segsum[sh_dd[e0 + i] * NHEADS + head], ex);
                }
            }
        }
    }
}

// ---------------------------------------------------------------------------
// K2: output contributions.  One warp per position.  (G reads now fp16)
// ---------------------------------------------------------------------------
__global__ void __launch_bounds__(256)
pass2_kernel(const int* __restrict__ eidx, const float* __restrict__ wig,
             float* __restrict__ out)
{
    __shared__ float sh_al[8][NHEADS];

    const int w    = threadIdx.x >> 5;
    const int lane = threadIdx.x & 31;
    const int pos  = blockIdx.x * 8 + w;
    if (pos >= NE) return;

    const int ed  = g_order[pos];
    const int s   = eidx[ed];
    const int d   = eidx[NE + ed];
    const int blk = (pos >= g_cnt[0]) ? 1 : 0;

    if (lane < NHEADS) {
        float ex = g_ex[(size_t)pos * NHEADS + lane];
        sh_al[w][lane] = ex / (g_segsum[d * NHEADS + lane] + 1e-9f);
    }
    __syncwarp();

    float2 q = make_float2(0.f, 0.f);
#pragma unroll
    for (int head = 0; head < NHEADS; head++) {
        float al = sh_al[w][head];
        float2 p = *(const float2*)&g_PT[blk][head * HDIM + 2 * lane];
        q.x += al * p.x; q.y += al * p.y;
    }

    const __half2* GSb = g_G2[2 * blk]     + (size_t)s * (MDIM * H2);
    const __half2* GTb = g_G2[2 * blk + 1] + (size_t)d * (MDIM * H2);

    float2 a1 = __half22float2(GSb[1 * H2 + lane]);
    float2 b1 = __half22float2(GTb[1 * H2 + lane]);
    float2 a2 = __half22float2(GSb[2 * H2 + lane]);
    float2 b2 = __half22float2(GTb[2 * H2 + lane]);
    float2 a3 = __half22float2(GSb[3 * H2 + lane]);
    float2 b3 = __half22float2(GTb[3 * H2 + lane]);
    float2 ew = *(const float2*)(g_ew + (size_t)pos * HDIM + 2 * lane);

    float p1 = q.x * (a1.x + b1.x) + q.y * (a1.y + b1.y);
    float p2 = q.x * (a2.x + b2.x) + q.y * (a2.y + b2.y);
    float p3 = q.x * (a3.x + b3.x) + q.y * (a3.y + b3.y);
    float tp = q.x * ew.x + q.y * ew.y;

#pragma unroll
    for (int off = 16; off >= 1; off >>= 1) {
        p1 += __shfl_down_sync(0xffffffffu, p1, off);
        p2 += __shfl_down_sync(0xffffffffu, p2, off);
        p3 += __shfl_down_sync(0xffffffffu, p3, off);
        tp += __shfl_down_sync(0xffffffffu, tp, off);
    }

    if (lane == 0) {
        float4 w0 = *(const float4*)(wig + (size_t)ed * 256);
        atomicAdd(&out[d * 3 + 0], p1 + w0.y * tp);
        atomicAdd(&out[d * 3 + 1], p2 + w0.z * tp);
        atomicAdd(&out[d * 3 + 2], p3 + w0.w * tp);
    }
}

// ---------------------------------------------------------------------------
extern "C" void kernel_launch(void* const* d_in, const int* in_sizes, int n_in,
                              void* d_out, int out_size)
{
    const float* x    = (const float*)d_in[0];
    const int*   zn   = (const int*)d_in[1];
    const float* dist = (const float*)d_in[2];
    const int*   eidx = (const int*)d_in[3];
    const int*   mask = (const int*)d_in[4];
    const float* wig  = (const float*)d_in[5];

    const float* fs_emb_s = (const float*)d_in[6];
    const float* fs_emb_t = (const float*)d_in[7];
    const float* fs_wd    = (const float*)d_in[8];
    const float* fs_We    = (const float*)d_in[9];
    const float* fs_Ws    = (const float*)d_in[10];
    const float* fs_Wt    = (const float*)d_in[11];
    const float* fs_Wa    = (const float*)d_in[12];
    const float* fs_va    = (const float*)d_in[13];
    const float* fs_Wv    = (const float*)d_in[14];
    const float* fs_Wo    = (const float*)d_in[15];

    const float* dn_emb_s = (const float*)d_in[16];
    const float* dn_emb_t = (const float*)d_in[17];
    const float* dn_wd    = (const float*)d_in[18];
    const float* dn_We    = (const float*)d_in[19];
    const float* dn_Ws    = (const float*)d_in[20];
    const float* dn_Wt    = (const float*)d_in[21];
    const float* dn_Wa    = (const float*)d_in[22];
    const float* dn_va    = (const float*)d_in[23];
    const float* dn_Wv    = (const float*)d_in[24];
    const float* dn_Wo    = (const float*)d_in[25];

    float* out = (float*)d_out;

    setup_kernel<<<32, 256>>>(fs_Wv, fs_Wo, dn_Wv, dn_Wo, out);

    bucket_kernel<<<(NE + 255) / 256, 256>>>(eidx, mask);

    mm_kernel<<<dim3(NROWS / 64, 4), 128>>>(x, fs_Ws, fs_Wt, dn_Ws, dn_Wt);

    gather_kernel<<<7500, 256>>>(zn, dist, eidx, wig,
                                 fs_emb_s, fs_emb_t, fs_wd,
                                 dn_emb_s, dn_emb_t, dn_wd);

    edge_gemm_kernel<<<(NE + EPC - 1) / EPC, 256>>>(eidx,
                                 fs_We, fs_Wa, fs_va,
                                 dn_We, dn_Wa, dn_va);

    pass2_kernel<<<7500, 256>>>(eidx, wig, out);
}